// round 3
// baseline (speedup 1.0000x reference)
#include <cuda_runtime.h>
#include <cuda_bf16.h>

// Problem constants
#define BB 2
#define TT 2048
#define CC 1024
#define HH 16
#define DD 64
#define MM (BB*TT)        // 4096 rows

// Scratch (static __device__ — no runtime allocation)
__device__ float g_q[BB*HH*TT*DD];     // [B,H,T,D]
__device__ float g_k[BB*HH*TT*DD];
__device__ float g_v[BB*HH*TT*DD];
__device__ float g_att[BB*TT*CC];      // [B,T,C] (heads concatenated)

// ---------------------------------------------------------------------------
// Fused QKV projection GEMM.
// out_sel[b,h,t,d] = sum_c x[b,t,c] * W_sel[h,c,d]
// Grid: x = N-tile (0..47 over 3*1024 cols), y = M-tile (0..63 over 4096 rows)
// BM=BN=64, BK=16, 256 threads, 4x4 micro-tile per thread.
// Per 64-wide N tile, sel and h are constant -> B loads fully coalesced.
// ---------------------------------------------------------------------------
__global__ __launch_bounds__(256) void qkv_kernel(
    const float* __restrict__ x,
    const float* __restrict__ Wq,
    const float* __restrict__ Wk,
    const float* __restrict__ Wv)
{
    __shared__ float As[16][64];   // transposed A tile: As[k][m]
    __shared__ float Bs[16][64];   // Bs[k][n]

    const int m0 = blockIdx.y * 64;
    const int n0 = blockIdx.x * 64;          // 0..3008
    const int sel = n0 >> 10;                // 0=q,1=k,2=v
    const int h   = (n0 & 1023) >> 6;

    const float* W = (sel == 0 ? Wq : (sel == 1 ? Wk : Wv)) + h * (CC * DD);
    float* outBuf  = (sel == 0 ? g_q : (sel == 1 ? g_k : g_v));

    const int tid = threadIdx.x;
    const int tx = tid & 15;       // n direction (4 cols each)
    const int ty = tid >> 4;       // m direction (4 rows each)

    // load index mapping
    const int ar  = tid >> 2;            // A: row within tile (0..63)
    const int ac4 = (tid & 3) * 4;       // A: col within tile (0,4,8,12)
    const int br  = tid >> 4;            // B: k-row (0..15)
    const int bc4 = (tid & 15) * 4;      // B: col (0..60)

    float acc[4][4] = {};

    for (int k0 = 0; k0 < CC; k0 += 16) {
        float4 av = *(const float4*)&x[(m0 + ar) * CC + k0 + ac4];
        float4 bv = *(const float4*)&W[(k0 + br) * DD + bc4];
        __syncthreads();
        As[ac4 + 0][ar] = av.x;
        As[ac4 + 1][ar] = av.y;
        As[ac4 + 2][ar] = av.z;
        As[ac4 + 3][ar] = av.w;
        *(float4*)&Bs[br][bc4] = bv;
        __syncthreads();

        #pragma unroll
        for (int kk = 0; kk < 16; kk++) {
            float4 a = *(const float4*)&As[kk][ty * 4];
            float4 b = *(const float4*)&Bs[kk][tx * 4];
            acc[0][0] += a.x * b.x; acc[0][1] += a.x * b.y; acc[0][2] += a.x * b.z; acc[0][3] += a.x * b.w;
            acc[1][0] += a.y * b.x; acc[1][1] += a.y * b.y; acc[1][2] += a.y * b.z; acc[1][3] += a.y * b.w;
            acc[2][0] += a.z * b.x; acc[2][1] += a.z * b.y; acc[2][2] += a.z * b.z; acc[2][3] += a.z * b.w;
            acc[3][0] += a.w * b.x; acc[3][1] += a.w * b.y; acc[3][2] += a.w * b.z; acc[3][3] += a.w * b.w;
        }
    }

    // store: layout [B,H,T,D]
    #pragma unroll
    for (int ii = 0; ii < 4; ii++) {
        int mm = m0 + ty * 4 + ii;
        int b  = mm >> 11;
        int t  = mm & 2047;
        float4 r = make_float4(acc[ii][0], acc[ii][1], acc[ii][2], acc[ii][3]);
        *(float4*)&outBuf[(((b * HH) + h) * TT + t) * DD + tx * 4] = r;
    }
}

// ---------------------------------------------------------------------------
// Flash attention (causal), fp32.
// Grid: x = query tile (0..31), y = b*H+h (0..31). 128 threads/block.
// 64 queries/block; threads (i, half): pair per query row.
//   half splits the 64 keys (scores) and the 64 output dims (PV).
// Q row in registers; K/V tiles in SMEM (broadcast reads -> conflict-free).
// Online softmax; pair exchange via __shfl_xor.
// ---------------------------------------------------------------------------
__global__ __launch_bounds__(128) void attn_kernel()
{
    __shared__ float Ks[64][64];
    __shared__ float Vs[64][64];

    const int bh  = blockIdx.y;        // b*16 + h
    const int qt  = blockIdx.x;        // query tile index
    const int qt0 = qt * 64;
    const int tid  = threadIdx.x;
    const int i    = tid >> 1;         // query row within tile (0..63)
    const int half = tid & 1;          // 0 or 1

    // Q row -> registers (pair threads load the same row; L1 absorbs it)
    const float4* qrow = (const float4*)&g_q[(bh * TT + qt0 + i) * DD];
    float4 q4[16];
    #pragma unroll
    for (int t = 0; t < 16; t++) q4[t] = qrow[t];

    float out[32];
    #pragma unroll
    for (int d = 0; d < 32; d++) out[d] = 0.f;

    float m = -1e30f;
    float l = 0.f;
    const float scale = 0.125f;        // DH^-0.5 = 1/8

    for (int jt = 0; jt <= qt; jt++) {
        const int jt0 = jt * 64;
        const float* kbase = &g_k[(bh * TT + jt0) * DD];
        const float* vbase = &g_v[(bh * TT + jt0) * DD];

        __syncthreads();
        #pragma unroll
        for (int p = 0; p < 8; p++) {
            int idx = tid + p * 128;              // 0..1023 (float4 index)
            int r   = idx >> 4;
            int c4  = (idx & 15) << 2;
            *(float4*)&Ks[r][c4] = *(const float4*)&kbase[r * DD + c4];
            *(float4*)&Vs[r][c4] = *(const float4*)&vbase[r * DD + c4];
        }
        __syncthreads();

        // scores for this thread's 32 keys: j = half*32 + jj
        float p_[32];
        float tmax = -1e30f;
        #pragma unroll
        for (int jj = 0; jj < 32; jj++) {
            int j = half * 32 + jj;
            const float4* krow = (const float4*)Ks[j];
            float s = 0.f;
            #pragma unroll
            for (int t = 0; t < 16; t++) {
                float4 k4 = krow[t];
                s += q4[t].x * k4.x + q4[t].y * k4.y + q4[t].z * k4.z + q4[t].w * k4.w;
            }
            s *= scale;
            if (jt == qt && j > i) s = -1e30f;    // causal mask (diagonal tile only)
            p_[jj] = s;
            tmax = fmaxf(tmax, s);
        }
        tmax = fmaxf(tmax, __shfl_xor_sync(0xffffffffu, tmax, 1));
        float mnew  = fmaxf(m, tmax);
        float alpha = __expf(m - mnew);
        float psum = 0.f;
        #pragma unroll
        for (int jj = 0; jj < 32; jj++) {
            p_[jj] = __expf(p_[jj] - mnew);
            psum += p_[jj];
        }
        psum += __shfl_xor_sync(0xffffffffu, psum, 1);
        l = l * alpha + psum;
        m = mnew;

        #pragma unroll
        for (int d = 0; d < 32; d++) out[d] *= alpha;

        // PV: this thread accumulates dims [half*32, half*32+32)
        const int dbase = half * 32;
        #pragma unroll
        for (int jj = 0; jj < 32; jj++) {
            float pmine  = p_[jj];
            float pother = __shfl_xor_sync(0xffffffffu, pmine, 1);
            float plo = half ? pother : pmine;    // prob for key jj
            float phi = half ? pmine  : pother;   // prob for key 32+jj
            const float4* vlo = (const float4*)&Vs[jj][dbase];
            const float4* vhi = (const float4*)&Vs[32 + jj][dbase];
            #pragma unroll
            for (int d4 = 0; d4 < 8; d4++) {
                float4 v0 = vlo[d4];
                float4 v1 = vhi[d4];
                out[d4 * 4 + 0] += plo * v0.x + phi * v1.x;
                out[d4 * 4 + 1] += plo * v0.y + phi * v1.y;
                out[d4 * 4 + 2] += plo * v0.z + phi * v1.z;
                out[d4 * 4 + 3] += plo * v0.w + phi * v1.w;
            }
        }
    }

    // normalize + store to [B,T,C] (concat heads)
    const float inv = 1.f / l;
    const int b = bh >> 4;
    const int h = bh & 15;
    float* o = &g_att[(b * TT + qt0 + i) * CC + h * DD + half * 32];
    #pragma unroll
    for (int d4 = 0; d4 < 8; d4++) {
        float4 r = make_float4(out[d4 * 4 + 0] * inv, out[d4 * 4 + 1] * inv,
                               out[d4 * 4 + 2] * inv, out[d4 * 4 + 3] * inv);
        *(float4*)&o[d4 * 4] = r;
    }
}

// ---------------------------------------------------------------------------
// Output projection: out[m,n] = sum_k g_att[m,k] * Wp[k,n] + bp[n]
// Grid: x = N-tile (0..15), y = M-tile (0..63). Same tiling as qkv_kernel.
// ---------------------------------------------------------------------------
__global__ __launch_bounds__(256) void proj_kernel(
    const float* __restrict__ Wp,
    const float* __restrict__ bp,
    float* __restrict__ out)
{
    __shared__ float As[16][64];
    __shared__ float Bs[16][64];

    const int m0 = blockIdx.y * 64;
    const int n0 = blockIdx.x * 64;

    const int tid = threadIdx.x;
    const int tx = tid & 15;
    const int ty = tid >> 4;

    const int ar  = tid >> 2;
    const int ac4 = (tid & 3) * 4;
    const int br  = tid >> 4;
    const int bc4 = (tid & 15) * 4;

    float acc[4][4] = {};

    for (int k0 = 0; k0 < CC; k0 += 16) {
        float4 av = *(const float4*)&g_att[(m0 + ar) * CC + k0 + ac4];
        float4 bv = *(const float4*)&Wp[(k0 + br) * CC + n0 + bc4];
        __syncthreads();
        As[ac4 + 0][ar] = av.x;
        As[ac4 + 1][ar] = av.y;
        As[ac4 + 2][ar] = av.z;
        As[ac4 + 3][ar] = av.w;
        *(float4*)&Bs[br][bc4] = bv;
        __syncthreads();

        #pragma unroll
        for (int kk = 0; kk < 16; kk++) {
            float4 a = *(const float4*)&As[kk][ty * 4];
            float4 b = *(const float4*)&Bs[kk][tx * 4];
            acc[0][0] += a.x * b.x; acc[0][1] += a.x * b.y; acc[0][2] += a.x * b.z; acc[0][3] += a.x * b.w;
            acc[1][0] += a.y * b.x; acc[1][1] += a.y * b.y; acc[1][2] += a.y * b.z; acc[1][3] += a.y * b.w;
            acc[2][0] += a.z * b.x; acc[2][1] += a.z * b.y; acc[2][2] += a.z * b.z; acc[2][3] += a.z * b.w;
            acc[3][0] += a.w * b.x; acc[3][1] += a.w * b.y; acc[3][2] += a.w * b.z; acc[3][3] += a.w * b.w;
        }
    }

    const float4 bias = *(const float4*)&bp[n0 + tx * 4];
    #pragma unroll
    for (int ii = 0; ii < 4; ii++) {
        int mm = m0 + ty * 4 + ii;
        float4 r = make_float4(acc[ii][0] + bias.x, acc[ii][1] + bias.y,
                               acc[ii][2] + bias.z, acc[ii][3] + bias.w);
        *(float4*)&out[mm * CC + n0 + tx * 4] = r;
    }
}

// ---------------------------------------------------------------------------
extern "C" void kernel_launch(void* const* d_in, const int* in_sizes, int n_in,
                              void* d_out, int out_size)
{
    const float* x  = (const float*)d_in[0];
    const float* Wq = (const float*)d_in[1];
    const float* Wk = (const float*)d_in[2];
    const float* Wv = (const float*)d_in[3];
    const float* Wp = (const float*)d_in[4];
    const float* bp = (const float*)d_in[5];
    float* out = (float*)d_out;

    (void)in_sizes; (void)n_in; (void)out_size;

    // 1) fused QKV projections: N = 3*1024 cols, M = 4096 rows
    qkv_kernel<<<dim3(48, 64), 256>>>(x, Wq, Wk, Wv);

    // 2) causal flash attention: 32 query tiles x 32 (b,h) pairs
    attn_kernel<<<dim3(32, 32), 128>>>();

    // 3) output projection + bias
    proj_kernel<<<dim3(16, 64), 256>>>(Wp, bp, out);
}

// round 4
// speedup vs baseline: 4.4104x; 4.4104x over previous
#include <cuda_runtime.h>
#include <cuda_bf16.h>
#include <cstdint>

// Problem constants
#define BB 2
#define TT 2048
#define CC 1024
#define HH 16
#define DD 64
#define MM (BB*TT)        // 4096 rows

// Scratch (static __device__ — no runtime allocation)
__device__ float g_q[BB*HH*TT*DD];     // [B,H,T,D]
__device__ float g_k[BB*HH*TT*DD];
__device__ float g_v[BB*HH*TT*DD];
__device__ float g_att[BB*TT*CC];      // [B,T,C] (heads concatenated)

// ---------------------------------------------------------------------------
// tf32 helpers
// ---------------------------------------------------------------------------
__device__ __forceinline__ uint32_t f2tf(float f) {
    uint32_t u;
    asm("cvt.rna.tf32.f32 %0, %1;" : "=r"(u) : "f"(f));
    return u;
}

// D += A(16x8, tf32, row) * B(8x8, tf32, col); fp32 accumulate.
__device__ __forceinline__ void mma_tf32(float* d, const uint32_t* a, const uint32_t* b) {
    asm volatile(
        "mma.sync.aligned.m16n8k8.row.col.f32.tf32.tf32.f32 "
        "{%0,%1,%2,%3}, {%4,%5,%6,%7}, {%8,%9}, {%0,%1,%2,%3};"
        : "+f"(d[0]), "+f"(d[1]), "+f"(d[2]), "+f"(d[3])
        : "r"(a[0]), "r"(a[1]), "r"(a[2]), "r"(a[3]),
          "r"(b[0]), "r"(b[1]));
}

// SMEM strides (elements). SA ≡ 4 (mod 32) -> A-frag loads conflict-free.
//                          SB ≡ 8 (mod 32) -> B-frag loads conflict-free.
#define SA 36
#define SB 72

// ---------------------------------------------------------------------------
// Fused QKV projection GEMM (tf32 tensor cores).
// out_sel[b,h,t,d] = sum_c x[b,t,c] * W_sel[h,c,d]
// BM=128, BN=64, BK=32. 256 threads = 8 warps (4 m-strips x 2 n-strips of 32x32).
// Grid: x = N-tile over 3*1024 cols (48), y = M-tile over 4096 rows (32).
// ---------------------------------------------------------------------------
__global__ __launch_bounds__(256, 2) void qkv_tc(
    const float* __restrict__ x,
    const float* __restrict__ Wq,
    const float* __restrict__ Wk,
    const float* __restrict__ Wv)
{
    __shared__ uint32_t As[128 * SA];   // [m][k] tf32
    __shared__ uint32_t Bs[32 * SB];    // [k][n] tf32

    const int tid  = threadIdx.x;
    const int lane = tid & 31;
    const int warp = tid >> 5;
    const int wm = warp & 3;            // m strip (0..3)
    const int wn = warp >> 2;           // n strip (0..1)
    const int g  = lane >> 2;           // group id (0..7)
    const int tg = lane & 3;            // thread in group (0..3)

    const int m0 = blockIdx.y * 128;
    const int n0 = blockIdx.x * 64;
    const int sel = n0 >> 10;                 // 0=q,1=k,2=v
    const int h   = (n0 & 1023) >> 6;

    const float* W = (sel == 0 ? Wq : (sel == 1 ? Wk : Wv)) + h * (CC * DD);
    float* outBuf  = (sel == 0 ? g_q : (sel == 1 ? g_k : g_v));

    float acc[2][4][4] = {};            // [mt][nt][4]

    for (int k0 = 0; k0 < CC; k0 += 32) {
        // --- gmem loads into registers ---
        float4 av[4], bv[2];
        #pragma unroll
        for (int p = 0; p < 4; p++) {
            int idx = tid + p * 256;            // 0..1023 over 128x8 float4
            int r = idx >> 3, c4 = (idx & 7) * 4;
            av[p] = *(const float4*)&x[(m0 + r) * CC + k0 + c4];
        }
        #pragma unroll
        for (int p = 0; p < 2; p++) {
            int idx = tid + p * 256;            // 0..511 over 32x16 float4
            int r = idx >> 4, c4 = (idx & 15) * 4;
            bv[p] = *(const float4*)&W[(k0 + r) * DD + c4];
        }
        __syncthreads();
        // --- cvt + smem store ---
        #pragma unroll
        for (int p = 0; p < 4; p++) {
            int idx = tid + p * 256;
            int r = idx >> 3, c4 = (idx & 7) * 4;
            uint4 w = make_uint4(f2tf(av[p].x), f2tf(av[p].y), f2tf(av[p].z), f2tf(av[p].w));
            *(uint4*)&As[r * SA + c4] = w;
        }
        #pragma unroll
        for (int p = 0; p < 2; p++) {
            int idx = tid + p * 256;
            int r = idx >> 4, c4 = (idx & 15) * 4;
            uint4 w = make_uint4(f2tf(bv[p].x), f2tf(bv[p].y), f2tf(bv[p].z), f2tf(bv[p].w));
            *(uint4*)&Bs[r * SB + c4] = w;
        }
        __syncthreads();

        // --- MMA over BK=32 (4 k-chunks of 8) ---
        #pragma unroll
        for (int kc = 0; kc < 4; kc++) {
            uint32_t af[2][4];
            #pragma unroll
            for (int mt = 0; mt < 2; mt++) {
                int r = wm * 32 + mt * 16 + g;
                int c = kc * 8 + tg;
                af[mt][0] = As[r * SA + c];
                af[mt][1] = As[(r + 8) * SA + c];
                af[mt][2] = As[r * SA + c + 4];
                af[mt][3] = As[(r + 8) * SA + c + 4];
            }
            #pragma unroll
            for (int nt = 0; nt < 4; nt++) {
                uint32_t bf[2];
                int c = wn * 32 + nt * 8 + g;
                int r = kc * 8 + tg;
                bf[0] = Bs[r * SB + c];
                bf[1] = Bs[(r + 4) * SB + c];
                mma_tf32(acc[0][nt], af[0], bf);
                mma_tf32(acc[1][nt], af[1], bf);
            }
        }
    }

    // --- epilogue: store to [B,H,T,D] ---
    #pragma unroll
    for (int mt = 0; mt < 2; mt++) {
        int mm = m0 + wm * 32 + mt * 16 + g;
        int b  = mm >> 11;
        int t  = mm & 2047;
        float* o0 = &outBuf[((b * HH + h) * TT + t) * DD];
        float* o1 = &outBuf[((b * HH + h) * TT + ((mm + 8) & 2047)) * DD];
        #pragma unroll
        for (int nt = 0; nt < 4; nt++) {
            int col = wn * 32 + nt * 8 + 2 * tg;
            *(float2*)&o0[col] = make_float2(acc[mt][nt][0], acc[mt][nt][1]);
            *(float2*)&o1[col] = make_float2(acc[mt][nt][2], acc[mt][nt][3]);
        }
    }
}

// ---------------------------------------------------------------------------
// Flash attention (causal) with tf32 tensor cores.
// Block: one (b,h), 64 queries, 4 warps (16 query rows each). Key tiles of 64.
// Q fragments (scale folded) register-resident. S = Q K^T via MMA; fragment
// online softmax; P stored to reused K SMEM buffer, re-read as A operand of PV.
// ---------------------------------------------------------------------------
#define SK 68   // Ks/Ps stride: 68 ≡ 4 (mod 32)
#define SV 72   // Vs stride:    72 ≡ 8 (mod 32)

__global__ __launch_bounds__(128, 3) void attn_tc()
{
    __shared__ uint32_t Ks[64 * SK];    // K tile; reused for Q staging and P
    __shared__ uint32_t Vs[64 * SV];    // V tile

    const int tid  = threadIdx.x;
    const int lane = tid & 31;
    const int warp = tid >> 5;          // 0..3
    const int g  = lane >> 2;
    const int tg = lane & 3;

    const int qt  = blockIdx.x;
    const int bh  = blockIdx.y;
    const int qt0 = qt * 64;

    // --- stage Q (pre-scaled by 1/8) into Ks, extract fragments ---
    {
        const float* qb = &g_q[(bh * TT + qt0) * DD];
        #pragma unroll
        for (int p = 0; p < 8; p++) {
            int idx = tid + p * 128;
            int r = idx >> 4, c4 = (idx & 15) * 4;
            float4 v = *(const float4*)&qb[r * DD + c4];
            uint4 w = make_uint4(f2tf(v.x * 0.125f), f2tf(v.y * 0.125f),
                                 f2tf(v.z * 0.125f), f2tf(v.w * 0.125f));
            *(uint4*)&Ks[r * SK + c4] = w;
        }
    }
    __syncthreads();
    uint32_t qa[8][4];
    #pragma unroll
    for (int kc = 0; kc < 8; kc++) {
        int r = warp * 16 + g, c = kc * 8 + tg;
        qa[kc][0] = Ks[r * SK + c];
        qa[kc][1] = Ks[(r + 8) * SK + c];
        qa[kc][2] = Ks[r * SK + c + 4];
        qa[kc][3] = Ks[(r + 8) * SK + c + 4];
    }

    float o[8][4] = {};
    float m0v = -1e30f, m1v = -1e30f, l0 = 0.f, l1 = 0.f;
    const int i0 = qt0 + warp * 16 + g;     // query row for c0/c1
    const int i1 = i0 + 8;                  // query row for c2/c3

    for (int jt = 0; jt <= qt; jt++) {
        __syncthreads();                    // prior iter's Ps/Ks reads done
        {
            const float* kb = &g_k[(bh * TT + jt * 64) * DD];
            const float* vb = &g_v[(bh * TT + jt * 64) * DD];
            #pragma unroll
            for (int p = 0; p < 8; p++) {
                int idx = tid + p * 128;
                int r = idx >> 4, c4 = (idx & 15) * 4;
                float4 kv = *(const float4*)&kb[r * DD + c4];
                float4 vv = *(const float4*)&vb[r * DD + c4];
                *(uint4*)&Ks[r * SK + c4] =
                    make_uint4(f2tf(kv.x), f2tf(kv.y), f2tf(kv.z), f2tf(kv.w));
                *(uint4*)&Vs[r * SV + c4] =
                    make_uint4(f2tf(vv.x), f2tf(vv.y), f2tf(vv.z), f2tf(vv.w));
            }
        }
        __syncthreads();

        // --- S = Q K^T (scale already in Q) ---
        float s[8][4] = {};
        #pragma unroll
        for (int kc = 0; kc < 8; kc++) {
            #pragma unroll
            for (int nt = 0; nt < 8; nt++) {
                uint32_t bf[2];
                int key = nt * 8 + g;
                int d   = kc * 8 + tg;
                bf[0] = Ks[key * SK + d];
                bf[1] = Ks[key * SK + d + 4];
                mma_tf32(s[nt], qa[kc], bf);
            }
        }

        // --- causal mask on diagonal tile ---
        if (jt == qt) {
            #pragma unroll
            for (int nt = 0; nt < 8; nt++) {
                int j = qt0 + nt * 8 + 2 * tg;
                if (j     > i0) s[nt][0] = -1e30f;
                if (j + 1 > i0) s[nt][1] = -1e30f;
                if (j     > i1) s[nt][2] = -1e30f;
                if (j + 1 > i1) s[nt][3] = -1e30f;
            }
        }

        // --- online softmax (rows i0, i1) ---
        float rmax0 = -1e30f, rmax1 = -1e30f;
        #pragma unroll
        for (int nt = 0; nt < 8; nt++) {
            rmax0 = fmaxf(rmax0, fmaxf(s[nt][0], s[nt][1]));
            rmax1 = fmaxf(rmax1, fmaxf(s[nt][2], s[nt][3]));
        }
        rmax0 = fmaxf(rmax0, __shfl_xor_sync(0xffffffffu, rmax0, 1));
        rmax0 = fmaxf(rmax0, __shfl_xor_sync(0xffffffffu, rmax0, 2));
        rmax1 = fmaxf(rmax1, __shfl_xor_sync(0xffffffffu, rmax1, 1));
        rmax1 = fmaxf(rmax1, __shfl_xor_sync(0xffffffffu, rmax1, 2));

        float mn0 = fmaxf(m0v, rmax0);
        float mn1 = fmaxf(m1v, rmax1);
        float al0 = __expf(m0v - mn0);
        float al1 = __expf(m1v - mn1);

        float ls0 = 0.f, ls1 = 0.f;
        #pragma unroll
        for (int nt = 0; nt < 8; nt++) {
            s[nt][0] = __expf(s[nt][0] - mn0);
            s[nt][1] = __expf(s[nt][1] - mn0);
            s[nt][2] = __expf(s[nt][2] - mn1);
            s[nt][3] = __expf(s[nt][3] - mn1);
            ls0 += s[nt][0] + s[nt][1];
            ls1 += s[nt][2] + s[nt][3];
        }
        ls0 += __shfl_xor_sync(0xffffffffu, ls0, 1);
        ls0 += __shfl_xor_sync(0xffffffffu, ls0, 2);
        ls1 += __shfl_xor_sync(0xffffffffu, ls1, 1);
        ls1 += __shfl_xor_sync(0xffffffffu, ls1, 2);

        l0 = l0 * al0 + ls0;  m0v = mn0;
        l1 = l1 * al1 + ls1;  m1v = mn1;

        #pragma unroll
        for (int nt = 0; nt < 8; nt++) {
            o[nt][0] *= al0; o[nt][1] *= al0;
            o[nt][2] *= al1; o[nt][3] *= al1;
        }

        __syncthreads();                    // all warps done reading Ks
        // --- store P (tf32) into per-warp strip of Ks buffer ---
        #pragma unroll
        for (int nt = 0; nt < 8; nt++) {
            int r = warp * 16 + g, c = nt * 8 + 2 * tg;
            *(uint2*)&Ks[r * SK + c]       = make_uint2(f2tf(s[nt][0]), f2tf(s[nt][1]));
            *(uint2*)&Ks[(r + 8) * SK + c] = make_uint2(f2tf(s[nt][2]), f2tf(s[nt][3]));
        }
        __syncwarp();

        // --- O += P V ---
        #pragma unroll
        for (int kc = 0; kc < 8; kc++) {
            uint32_t pa[4];
            int r = warp * 16 + g, c = kc * 8 + tg;
            pa[0] = Ks[r * SK + c];
            pa[1] = Ks[(r + 8) * SK + c];
            pa[2] = Ks[r * SK + c + 4];
            pa[3] = Ks[(r + 8) * SK + c + 4];
            #pragma unroll
            for (int nt = 0; nt < 8; nt++) {
                uint32_t vf[2];
                int key = kc * 8 + tg;
                int d   = nt * 8 + g;
                vf[0] = Vs[key * SV + d];
                vf[1] = Vs[(key + 4) * SV + d];
                mma_tf32(o[nt], pa, vf);
            }
        }
    }

    // --- normalize + store to [B,T,C] ---
    const float inv0 = 1.f / l0;
    const float inv1 = 1.f / l1;
    const int b = bh >> 4;
    const int h = bh & 15;
    const int r0 = qt0 + warp * 16 + g;
    float* ob0 = &g_att[(b * TT + r0) * CC + h * DD];
    float* ob1 = &g_att[(b * TT + r0 + 8) * CC + h * DD];
    #pragma unroll
    for (int nt = 0; nt < 8; nt++) {
        int col = nt * 8 + 2 * tg;
        *(float2*)&ob0[col] = make_float2(o[nt][0] * inv0, o[nt][1] * inv0);
        *(float2*)&ob1[col] = make_float2(o[nt][2] * inv1, o[nt][3] * inv1);
    }
}

// ---------------------------------------------------------------------------
// Output projection (tf32 tensor cores): out = g_att @ Wp + bp
// Same tiling as qkv_tc. Grid: x = N-tile (16), y = M-tile (32).
// ---------------------------------------------------------------------------
__global__ __launch_bounds__(256, 2) void proj_tc(
    const float* __restrict__ Wp,
    const float* __restrict__ bp,
    float* __restrict__ out)
{
    __shared__ uint32_t As[128 * SA];
    __shared__ uint32_t Bs[32 * SB];

    const int tid  = threadIdx.x;
    const int lane = tid & 31;
    const int warp = tid >> 5;
    const int wm = warp & 3;
    const int wn = warp >> 2;
    const int g  = lane >> 2;
    const int tg = lane & 3;

    const int m0 = blockIdx.y * 128;
    const int n0 = blockIdx.x * 64;

    float acc[2][4][4] = {};

    for (int k0 = 0; k0 < CC; k0 += 32) {
        float4 av[4], bv[2];
        #pragma unroll
        for (int p = 0; p < 4; p++) {
            int idx = tid + p * 256;
            int r = idx >> 3, c4 = (idx & 7) * 4;
            av[p] = *(const float4*)&g_att[(m0 + r) * CC + k0 + c4];
        }
        #pragma unroll
        for (int p = 0; p < 2; p++) {
            int idx = tid + p * 256;
            int r = idx >> 4, c4 = (idx & 15) * 4;
            bv[p] = *(const float4*)&Wp[(k0 + r) * CC + n0 + c4];
        }
        __syncthreads();
        #pragma unroll
        for (int p = 0; p < 4; p++) {
            int idx = tid + p * 256;
            int r = idx >> 3, c4 = (idx & 7) * 4;
            uint4 w = make_uint4(f2tf(av[p].x), f2tf(av[p].y), f2tf(av[p].z), f2tf(av[p].w));
            *(uint4*)&As[r * SA + c4] = w;
        }
        #pragma unroll
        for (int p = 0; p < 2; p++) {
            int idx = tid + p * 256;
            int r = idx >> 4, c4 = (idx & 15) * 4;
            uint4 w = make_uint4(f2tf(bv[p].x), f2tf(bv[p].y), f2tf(bv[p].z), f2tf(bv[p].w));
            *(uint4*)&Bs[r * SB + c4] = w;
        }
        __syncthreads();

        #pragma unroll
        for (int kc = 0; kc < 4; kc++) {
            uint32_t af[2][4];
            #pragma unroll
            for (int mt = 0; mt < 2; mt++) {
                int r = wm * 32 + mt * 16 + g;
                int c = kc * 8 + tg;
                af[mt][0] = As[r * SA + c];
                af[mt][1] = As[(r + 8) * SA + c];
                af[mt][2] = As[r * SA + c + 4];
                af[mt][3] = As[(r + 8) * SA + c + 4];
            }
            #pragma unroll
            for (int nt = 0; nt < 4; nt++) {
                uint32_t bf[2];
                int c = wn * 32 + nt * 8 + g;
                int r = kc * 8 + tg;
                bf[0] = Bs[r * SB + c];
                bf[1] = Bs[(r + 4) * SB + c];
                mma_tf32(acc[0][nt], af[0], bf);
                mma_tf32(acc[1][nt], af[1], bf);
            }
        }
    }

    #pragma unroll
    for (int mt = 0; mt < 2; mt++) {
        int mm = m0 + wm * 32 + mt * 16 + g;
        #pragma unroll
        for (int nt = 0; nt < 4; nt++) {
            int col = n0 + wn * 32 + nt * 8 + 2 * tg;
            float b0 = bp[col], b1 = bp[col + 1];
            *(float2*)&out[mm * CC + col] =
                make_float2(acc[mt][nt][0] + b0, acc[mt][nt][1] + b1);
            *(float2*)&out[(mm + 8) * CC + col] =
                make_float2(acc[mt][nt][2] + b0, acc[mt][nt][3] + b1);
        }
    }
}

// ---------------------------------------------------------------------------
extern "C" void kernel_launch(void* const* d_in, const int* in_sizes, int n_in,
                              void* d_out, int out_size)
{
    const float* x  = (const float*)d_in[0];
    const float* Wq = (const float*)d_in[1];
    const float* Wk = (const float*)d_in[2];
    const float* Wv = (const float*)d_in[3];
    const float* Wp = (const float*)d_in[4];
    const float* bp = (const float*)d_in[5];
    float* out = (float*)d_out;

    (void)in_sizes; (void)n_in; (void)out_size;

    // 1) fused QKV projections (tf32 MMA): N = 3*1024, M = 4096
    qkv_tc<<<dim3(48, 32), 256>>>(x, Wq, Wk, Wv);

    // 2) causal flash attention (tf32 MMA): 32 query tiles x 32 (b,h)
    attn_tc<<<dim3(32, 32), 128>>>();

    // 3) output projection + bias (tf32 MMA)
    proj_tc<<<dim3(16, 32), 256>>>(Wp, bp, out);
}

// round 5
// speedup vs baseline: 4.7695x; 1.0814x over previous
#include <cuda_runtime.h>
#include <cuda_bf16.h>
#include <cstdint>

// Problem constants
#define BB 2
#define TT 2048
#define CC 1024
#define HH 16
#define DD 64
#define MM (BB*TT)        // 4096 rows

// Scratch (static __device__ — no runtime allocation)
__device__ float g_q[BB*HH*TT*DD];     // [B,H,T,D]
__device__ float g_k[BB*HH*TT*DD];
__device__ float g_v[BB*HH*TT*DD];
__device__ float g_att[BB*TT*CC];      // [B,T,C] (heads concatenated)

// ---------------------------------------------------------------------------
// tf32 helpers
// ---------------------------------------------------------------------------
__device__ __forceinline__ uint32_t f2tf(float f) {
    uint32_t u;
    asm("cvt.rna.tf32.f32 %0, %1;" : "=r"(u) : "f"(f));
    return u;
}

// D += A(16x8, tf32, row) * B(8x8, tf32, col); fp32 accumulate.
__device__ __forceinline__ void mma_tf32(float* d, const uint32_t* a, const uint32_t* b) {
    asm volatile(
        "mma.sync.aligned.m16n8k8.row.col.f32.tf32.tf32.f32 "
        "{%0,%1,%2,%3}, {%4,%5,%6,%7}, {%8,%9}, {%0,%1,%2,%3};"
        : "+f"(d[0]), "+f"(d[1]), "+f"(d[2]), "+f"(d[3])
        : "r"(a[0]), "r"(a[1]), "r"(a[2]), "r"(a[3]),
          "r"(b[0]), "r"(b[1]));
}

// GEMM SMEM strides (elements). SA ≡ 4 (mod 32), SB ≡ 8 (mod 32) ->
// fragment loads conflict-free.
#define SA 20     // A tile: 128 x 16, stride 20
#define SB 136    // B tile: 16 x 128, stride 136

// ---------------------------------------------------------------------------
// Shared GEMM body (tf32, double-buffered).
// BM=128, BN=128, BK=16. 256 threads = 8 warps; warp tile 32(m) x 64(n).
// IS_QKV=1: A = x, B = per-head W (two heads per 128-wide N tile), out -> g_q/k/v.
// IS_QKV=0: A = g_att, B = Wp [C,C], out = d_out with bias.
// ---------------------------------------------------------------------------
template<int IS_QKV>
__global__ __launch_bounds__(256, 2) void gemm_tc(
    const float* __restrict__ Ain,
    const float* __restrict__ Wq,
    const float* __restrict__ Wk,
    const float* __restrict__ Wv,
    const float* __restrict__ Wp,
    const float* __restrict__ bp,
    float* __restrict__ out)
{
    __shared__ uint32_t As[2][128 * SA];
    __shared__ uint32_t Bs[2][16 * SB];

    const float* A = IS_QKV ? Ain : (const float*)g_att;

    const int tid  = threadIdx.x;
    const int lane = tid & 31;
    const int warp = tid >> 5;
    const int wm = warp & 3;            // m strip (0..3) of 32 rows
    const int wn = warp >> 2;           // n strip (0..1) of 64 cols
    const int g  = lane >> 2;
    const int tg = lane & 3;

    const int m0 = blockIdx.y * 128;
    const int n0 = blockIdx.x * 128;

    // B source resolution
    const float* W;
    int h0 = 0, sel = 0;
    if (IS_QKV) {
        sel = n0 >> 10;                 // 0=q,1=k,2=v  (1024 cols per sel)
        h0  = (n0 & 1023) >> 6;         // first head covered by this tile
        W   = (sel == 0 ? Wq : (sel == 1 ? Wk : Wv));
    } else {
        W = Wp;
    }

    const int a_r  = tid >> 2;              // A: base row 0..63 (2 passes)
    const int a_c4 = (tid & 3) * 4;         // A col: 0,4,8,12
    const int b_r  = tid >> 5;              // B row (k): 0..7 base (2 passes)
    const int b_c4 = (tid & 31) * 4;        // B col: 0..124

    float4 av[2], bv[2];

    auto load_tile = [&](int k0) {
        #pragma unroll
        for (int p = 0; p < 2; p++) {
            int r = a_r + p * 64;
            av[p] = *(const float4*)&A[(m0 + r) * CC + k0 + a_c4];
        }
        #pragma unroll
        for (int p = 0; p < 2; p++) {
            int r = b_r + p * 8;
            if (IS_QKV) {
                int h = h0 + (b_c4 >> 6);
                int d = b_c4 & 63;
                bv[p] = *(const float4*)&W[(h * CC + (k0 + r)) * DD + d];
            } else {
                bv[p] = *(const float4*)&W[(k0 + r) * CC + n0 + b_c4];
            }
        }
    };
    auto store_tile = [&](int buf) {
        #pragma unroll
        for (int p = 0; p < 2; p++) {
            int r = a_r + p * 64;
            uint4 w = make_uint4(f2tf(av[p].x), f2tf(av[p].y), f2tf(av[p].z), f2tf(av[p].w));
            *(uint4*)&As[buf][r * SA + a_c4] = w;
        }
        #pragma unroll
        for (int p = 0; p < 2; p++) {
            int r = b_r + p * 8;
            uint4 w = make_uint4(f2tf(bv[p].x), f2tf(bv[p].y), f2tf(bv[p].z), f2tf(bv[p].w));
            *(uint4*)&Bs[buf][r * SB + b_c4] = w;
        }
    };

    float acc[2][8][4] = {};            // [mt][nt][4]

    load_tile(0);
    store_tile(0);
    __syncthreads();

    int pb = 0;
    for (int k0 = 0; k0 < CC; k0 += 16) {
        const bool more = (k0 + 16) < CC;
        if (more) load_tile(k0 + 16);

        #pragma unroll
        for (int kc = 0; kc < 2; kc++) {
            uint32_t af[2][4];
            #pragma unroll
            for (int mt = 0; mt < 2; mt++) {
                int r = wm * 32 + mt * 16 + g;
                int c = kc * 8 + tg;
                af[mt][0] = As[pb][r * SA + c];
                af[mt][1] = As[pb][(r + 8) * SA + c];
                af[mt][2] = As[pb][r * SA + c + 4];
                af[mt][3] = As[pb][(r + 8) * SA + c + 4];
            }
            #pragma unroll
            for (int nt = 0; nt < 8; nt++) {
                uint32_t bf[2];
                int c = wn * 64 + nt * 8 + g;
                int r = kc * 8 + tg;
                bf[0] = Bs[pb][r * SB + c];
                bf[1] = Bs[pb][(r + 4) * SB + c];
                mma_tf32(acc[0][nt], af[0], bf);
                mma_tf32(acc[1][nt], af[1], bf);
            }
        }

        if (more) store_tile(pb ^ 1);
        __syncthreads();
        pb ^= 1;
    }

    #pragma unroll
    for (int mt = 0; mt < 2; mt++) {
        int mm = m0 + wm * 32 + mt * 16 + g;    // row (and mm+8)
        if (IS_QKV) {
            float* outBuf = (sel == 0 ? g_q : (sel == 1 ? g_k : g_v));
            int b = mm >> 11;
            int t = mm & 2047;
            #pragma unroll
            for (int nt = 0; nt < 8; nt++) {
                int col = wn * 64 + nt * 8 + 2 * tg;
                int h = h0 + (col >> 6);
                int d = col & 63;
                float* o0 = &outBuf[((b * HH + h) * TT + t) * DD + d];
                float* o1 = &outBuf[((b * HH + h) * TT + t + 8) * DD + d];
                *(float2*)o0 = make_float2(acc[mt][nt][0], acc[mt][nt][1]);
                *(float2*)o1 = make_float2(acc[mt][nt][2], acc[mt][nt][3]);
            }
        } else {
            #pragma unroll
            for (int nt = 0; nt < 8; nt++) {
                int col = n0 + wn * 64 + nt * 8 + 2 * tg;
                float b0 = bp[col], b1 = bp[col + 1];
                *(float2*)&out[mm * CC + col] =
                    make_float2(acc[mt][nt][0] + b0, acc[mt][nt][1] + b1);
                *(float2*)&out[(mm + 8) * CC + col] =
                    make_float2(acc[mt][nt][2] + b0, acc[mt][nt][3] + b1);
            }
        }
    }
}

// ---------------------------------------------------------------------------
// Flash attention (causal) with tf32 tensor cores.
// Block: one (b,h), 64 queries, 4 warps (16 query rows each). Key tiles of 64.
// Q fragments (scale folded) register-resident. S = Q K^T via MMA; fragment
// online softmax; S C-fragments permuted to PV A-fragments via intra-quad
// shuffles (no SMEM round trip, no extra barrier).
// ---------------------------------------------------------------------------
#define SK 68   // Ks stride: 68 ≡ 4 (mod 32)
#define SV 72   // Vs stride: 72 ≡ 8 (mod 32)

__global__ __launch_bounds__(128, 3) void attn_tc()
{
    __shared__ uint32_t Ks[64 * SK];    // K tile; also used for Q staging
    __shared__ uint32_t Vs[64 * SV];    // V tile

    const int tid  = threadIdx.x;
    const int lane = tid & 31;
    const int warp = tid >> 5;          // 0..3
    const int g  = lane >> 2;
    const int tg = lane & 3;

    const int qt  = blockIdx.x;
    const int bh  = blockIdx.y;
    const int qt0 = qt * 64;

    // --- stage Q (pre-scaled by 1/8) into Ks, extract fragments ---
    {
        const float* qb = &g_q[(bh * TT + qt0) * DD];
        #pragma unroll
        for (int p = 0; p < 8; p++) {
            int idx = tid + p * 128;
            int r = idx >> 4, c4 = (idx & 15) * 4;
            float4 v = *(const float4*)&qb[r * DD + c4];
            uint4 w = make_uint4(f2tf(v.x * 0.125f), f2tf(v.y * 0.125f),
                                 f2tf(v.z * 0.125f), f2tf(v.w * 0.125f));
            *(uint4*)&Ks[r * SK + c4] = w;
        }
    }
    __syncthreads();
    uint32_t qa[8][4];
    #pragma unroll
    for (int kc = 0; kc < 8; kc++) {
        int r = warp * 16 + g, c = kc * 8 + tg;
        qa[kc][0] = Ks[r * SK + c];
        qa[kc][1] = Ks[(r + 8) * SK + c];
        qa[kc][2] = Ks[r * SK + c + 4];
        qa[kc][3] = Ks[(r + 8) * SK + c + 4];
    }

    float o[8][4] = {};
    float m0v = -1e30f, m1v = -1e30f, l0 = 0.f, l1 = 0.f;
    const int i0 = qt0 + warp * 16 + g;     // query row for c0/c1
    const int i1 = i0 + 8;                  // query row for c2/c3

    for (int jt = 0; jt <= qt; jt++) {
        __syncthreads();                    // prior iter's Ks/Vs reads done
        {
            const float* kb = &g_k[(bh * TT + jt * 64) * DD];
            const float* vb = &g_v[(bh * TT + jt * 64) * DD];
            #pragma unroll
            for (int p = 0; p < 8; p++) {
                int idx = tid + p * 128;
                int r = idx >> 4, c4 = (idx & 15) * 4;
                float4 kv = *(const float4*)&kb[r * DD + c4];
                float4 vv = *(const float4*)&vb[r * DD + c4];
                *(uint4*)&Ks[r * SK + c4] =
                    make_uint4(f2tf(kv.x), f2tf(kv.y), f2tf(kv.z), f2tf(kv.w));
                *(uint4*)&Vs[r * SV + c4] =
                    make_uint4(f2tf(vv.x), f2tf(vv.y), f2tf(vv.z), f2tf(vv.w));
            }
        }
        __syncthreads();

        // --- S = Q K^T (scale already in Q) ---
        float s[8][4] = {};
        #pragma unroll
        for (int kc = 0; kc < 8; kc++) {
            #pragma unroll
            for (int nt = 0; nt < 8; nt++) {
                uint32_t bf[2];
                int key = nt * 8 + g;
                int d   = kc * 8 + tg;
                bf[0] = Ks[key * SK + d];
                bf[1] = Ks[key * SK + d + 4];
                mma_tf32(s[nt], qa[kc], bf);
            }
        }

        // --- causal mask on diagonal tile ---
        if (jt == qt) {
            #pragma unroll
            for (int nt = 0; nt < 8; nt++) {
                int j = qt0 + nt * 8 + 2 * tg;
                if (j     > i0) s[nt][0] = -1e30f;
                if (j + 1 > i0) s[nt][1] = -1e30f;
                if (j     > i1) s[nt][2] = -1e30f;
                if (j + 1 > i1) s[nt][3] = -1e30f;
            }
        }

        // --- online softmax (rows i0, i1) ---
        float rmax0 = -1e30f, rmax1 = -1e30f;
        #pragma unroll
        for (int nt = 0; nt < 8; nt++) {
            rmax0 = fmaxf(rmax0, fmaxf(s[nt][0], s[nt][1]));
            rmax1 = fmaxf(rmax1, fmaxf(s[nt][2], s[nt][3]));
        }
        rmax0 = fmaxf(rmax0, __shfl_xor_sync(0xffffffffu, rmax0, 1));
        rmax0 = fmaxf(rmax0, __shfl_xor_sync(0xffffffffu, rmax0, 2));
        rmax1 = fmaxf(rmax1, __shfl_xor_sync(0xffffffffu, rmax1, 1));
        rmax1 = fmaxf(rmax1, __shfl_xor_sync(0xffffffffu, rmax1, 2));

        float mn0 = fmaxf(m0v, rmax0);
        float mn1 = fmaxf(m1v, rmax1);
        float al0 = __expf(m0v - mn0);
        float al1 = __expf(m1v - mn1);

        float ls0 = 0.f, ls1 = 0.f;
        #pragma unroll
        for (int nt = 0; nt < 8; nt++) {
            s[nt][0] = __expf(s[nt][0] - mn0);
            s[nt][1] = __expf(s[nt][1] - mn0);
            s[nt][2] = __expf(s[nt][2] - mn1);
            s[nt][3] = __expf(s[nt][3] - mn1);
            ls0 += s[nt][0] + s[nt][1];
            ls1 += s[nt][2] + s[nt][3];
        }
        ls0 += __shfl_xor_sync(0xffffffffu, ls0, 1);
        ls0 += __shfl_xor_sync(0xffffffffu, ls0, 2);
        ls1 += __shfl_xor_sync(0xffffffffu, ls1, 1);
        ls1 += __shfl_xor_sync(0xffffffffu, ls1, 2);

        l0 = l0 * al0 + ls0;  m0v = mn0;
        l1 = l1 * al1 + ls1;  m1v = mn1;

        #pragma unroll
        for (int nt = 0; nt < 8; nt++) {
            o[nt][0] *= al0; o[nt][1] *= al0;
            o[nt][2] *= al1; o[nt][3] *= al1;
        }

        // --- O += P V. Permute S C-frags -> A-frags via intra-quad shfl ---
        const int qbase = lane & ~3;
        const int srcA  = qbase + (tg >> 1);
        const int srcB  = srcA + 2;
        const bool odd  = tg & 1;
        #pragma unroll
        for (int kc = 0; kc < 8; kc++) {
            float c0 = s[kc][0], c1 = s[kc][1], c2 = s[kc][2], c3 = s[kc][3];
            float u0 = __shfl_sync(0xffffffffu, c0, srcA);
            float u1 = __shfl_sync(0xffffffffu, c1, srcA);
            float u2 = __shfl_sync(0xffffffffu, c2, srcA);
            float u3 = __shfl_sync(0xffffffffu, c3, srcA);
            float w0 = __shfl_sync(0xffffffffu, c0, srcB);
            float w1 = __shfl_sync(0xffffffffu, c1, srcB);
            float w2 = __shfl_sync(0xffffffffu, c2, srcB);
            float w3 = __shfl_sync(0xffffffffu, c3, srcB);
            uint32_t pa[4];
            pa[0] = f2tf(odd ? u1 : u0);    // P[g   ][kc*8+tg  ]
            pa[1] = f2tf(odd ? u3 : u2);    // P[g+8 ][kc*8+tg  ]
            pa[2] = f2tf(odd ? w1 : w0);    // P[g   ][kc*8+tg+4]
            pa[3] = f2tf(odd ? w3 : w2);    // P[g+8 ][kc*8+tg+4]
            #pragma unroll
            for (int nt = 0; nt < 8; nt++) {
                uint32_t vf[2];
                int key = kc * 8 + tg;
                int d   = nt * 8 + g;
                vf[0] = Vs[key * SV + d];
                vf[1] = Vs[(key + 4) * SV + d];
                mma_tf32(o[nt], pa, vf);
            }
        }
    }

    // --- normalize + store to [B,T,C] ---
    const float inv0 = 1.f / l0;
    const float inv1 = 1.f / l1;
    const int b = bh >> 4;
    const int h = bh & 15;
    const int r0 = qt0 + warp * 16 + g;
    float* ob0 = &g_att[(b * TT + r0) * CC + h * DD];
    float* ob1 = &g_att[(b * TT + r0 + 8) * CC + h * DD];
    #pragma unroll
    for (int nt = 0; nt < 8; nt++) {
        int col = nt * 8 + 2 * tg;
        *(float2*)&ob0[col] = make_float2(o[nt][0] * inv0, o[nt][1] * inv0);
        *(float2*)&ob1[col] = make_float2(o[nt][2] * inv1, o[nt][3] * inv1);
    }
}

// ---------------------------------------------------------------------------
extern "C" void kernel_launch(void* const* d_in, const int* in_sizes, int n_in,
                              void* d_out, int out_size)
{
    const float* x  = (const float*)d_in[0];
    const float* Wq = (const float*)d_in[1];
    const float* Wk = (const float*)d_in[2];
    const float* Wv = (const float*)d_in[3];
    const float* Wp = (const float*)d_in[4];
    const float* bp = (const float*)d_in[5];
    float* out = (float*)d_out;

    (void)in_sizes; (void)n_in; (void)out_size;

    // 1) fused QKV projections (tf32 MMA, double-buffered): N=3072, M=4096
    gemm_tc<1><<<dim3(24, 32), 256>>>(x, Wq, Wk, Wv, nullptr, nullptr, nullptr);

    // 2) causal flash attention (tf32 MMA): 32 query tiles x 32 (b,h)
    attn_tc<<<dim3(32, 32), 128>>>();

    // 3) output projection + bias (tf32 MMA, double-buffered): N=1024
    gemm_tc<0><<<dim3(8, 32), 256>>>(nullptr, nullptr, nullptr, nullptr, Wp, bp, out);
}

// round 6
// speedup vs baseline: 5.3556x; 1.1229x over previous
#include <cuda_runtime.h>
#include <cuda_bf16.h>
#include <cstdint>

// Problem constants
#define BB 2
#define TT 2048
#define CC 1024
#define HH 16
#define DD 64
#define MM (BB*TT)        // 4096 rows

// Scratch (static __device__ — no runtime allocation)
__device__ float g_q[BB*HH*TT*DD];     // [B,H,T,D]
__device__ float g_k[BB*HH*TT*DD];
__device__ float g_v[BB*HH*TT*DD];
__device__ float g_att[BB*TT*CC];      // [B,T,C] (heads concatenated)

// ---------------------------------------------------------------------------
// tf32 / MMA helpers
// ---------------------------------------------------------------------------
__device__ __forceinline__ uint32_t f2tf(float f) {
    uint32_t u;
    asm("cvt.rna.tf32.f32 %0, %1;" : "=r"(u) : "f"(f));
    return u;
}

// D += A(16x8, tf32, row) * B(8x8, tf32, col); fp32 accumulate.
__device__ __forceinline__ void mma_tf32(float* d, const uint32_t* a, const uint32_t* b) {
    asm volatile(
        "mma.sync.aligned.m16n8k8.row.col.f32.tf32.tf32.f32 "
        "{%0,%1,%2,%3}, {%4,%5,%6,%7}, {%8,%9}, {%0,%1,%2,%3};"
        : "+f"(d[0]), "+f"(d[1]), "+f"(d[2]), "+f"(d[3])
        : "r"(a[0]), "r"(a[1]), "r"(a[2]), "r"(a[3]),
          "r"(b[0]), "r"(b[1]));
}

__device__ __forceinline__ void ldmatrix_x4(uint32_t* r, uint32_t addr) {
    asm volatile(
        "ldmatrix.sync.aligned.m8n8.x4.shared.b16 {%0,%1,%2,%3}, [%4];"
        : "=r"(r[0]), "=r"(r[1]), "=r"(r[2]), "=r"(r[3]) : "r"(addr));
}

// GEMM SMEM strides (elements). SA: row stride 20 (80B, 16B-aligned,
// ldmatrix row-start banks all distinct). SB ≡ 8 (mod 32) -> B-frag LDS
// conflict-free.
#define SA 20     // A tile: 128 x 16, stride 20
#define SB 136    // B tile: 16 x 128, stride 136

// ---------------------------------------------------------------------------
// Shared GEMM body (tf32, double-buffered, ldmatrix A-frags).
// BM=128, BN=128, BK=16. 128 threads = 4 warps; warp tile 64(m) x 64(n).
// IS_QKV=1: A = x, B = per-head W (two heads per 128-wide N tile), out -> g_q/k/v.
// IS_QKV=0: A = g_att, B = Wp [C,C], out = d_out with bias.
// ---------------------------------------------------------------------------
template<int IS_QKV>
__global__ __launch_bounds__(128, 2) void gemm_tc(
    const float* __restrict__ Ain,
    const float* __restrict__ Wq,
    const float* __restrict__ Wk,
    const float* __restrict__ Wv,
    const float* __restrict__ Wp,
    const float* __restrict__ bp,
    float* __restrict__ out)
{
    __shared__ uint32_t As[2][128 * SA];   // 2 x 10.0 KB
    __shared__ uint32_t Bs[2][16 * SB];    // 2 x 8.5 KB

    const float* A = IS_QKV ? Ain : (const float*)g_att;

    const int tid  = threadIdx.x;
    const int lane = tid & 31;
    const int warp = tid >> 5;          // 0..3
    const int wm = warp & 1;            // m strip (0..1) of 64 rows
    const int wn = warp >> 1;           // n strip (0..1) of 64 cols
    const int g  = lane >> 2;
    const int tg = lane & 3;

    const int m0 = blockIdx.y * 128;
    const int n0 = blockIdx.x * 128;

    // B source resolution
    const float* W;
    int h0 = 0, sel = 0;
    if (IS_QKV) {
        sel = n0 >> 10;                 // 0=q,1=k,2=v  (1024 cols per sel)
        h0  = (n0 & 1023) >> 6;         // first of two heads in this tile
        W   = (sel == 0 ? Wq : (sel == 1 ? Wk : Wv));
    } else {
        W = Wp;
    }

    // Load-index mapping (128 threads)
    const int a_r  = tid >> 2;              // A base row 0..31 (4 passes of 32)
    const int a_c4 = (tid & 3) * 4;         // A col: 0,4,8,12
    const int b_r  = tid >> 5;              // B base k-row 0..3 (4 passes of 4)
    const int b_c4 = (tid & 31) * 4;        // B col: 0..124

    // ldmatrix per-lane addressing for A fragments
    const int arow_l = (lane & 7) + ((lane >> 3) & 1) * 8;   // 0..15
    const int acol_l = (lane >> 4) * 4;                      // 0 or 4
    const uint32_t asmem = (uint32_t)__cvta_generic_to_shared(&As[0][0]);
    const uint32_t ABUF  = 128 * SA * 4;    // bytes per A buffer

    float4 av[4], bv[4];

    auto load_tile = [&](int k0) {
        #pragma unroll
        for (int p = 0; p < 4; p++) {
            int r = a_r + p * 32;
            av[p] = *(const float4*)&A[(m0 + r) * CC + k0 + a_c4];
        }
        #pragma unroll
        for (int p = 0; p < 4; p++) {
            int r = b_r + p * 4;
            if (IS_QKV) {
                int h = h0 + (b_c4 >> 6);
                int d = b_c4 & 63;
                bv[p] = *(const float4*)&W[(h * CC + (k0 + r)) * DD + d];
            } else {
                bv[p] = *(const float4*)&W[(k0 + r) * CC + n0 + b_c4];
            }
        }
    };
    auto store_tile = [&](int buf) {
        #pragma unroll
        for (int p = 0; p < 4; p++) {
            int r = a_r + p * 32;
            uint4 w = make_uint4(f2tf(av[p].x), f2tf(av[p].y), f2tf(av[p].z), f2tf(av[p].w));
            *(uint4*)&As[buf][r * SA + a_c4] = w;
        }
        #pragma unroll
        for (int p = 0; p < 4; p++) {
            int r = b_r + p * 4;
            uint4 w = make_uint4(f2tf(bv[p].x), f2tf(bv[p].y), f2tf(bv[p].z), f2tf(bv[p].w));
            *(uint4*)&Bs[buf][r * SB + b_c4] = w;
        }
    };

    float acc[4][8][4] = {};            // [mt][nt][4]

    load_tile(0);
    store_tile(0);
    __syncthreads();

    int pb = 0;
    for (int k0 = 0; k0 < CC; k0 += 16) {
        const bool more = (k0 + 16) < CC;
        if (more) load_tile(k0 + 16);

        #pragma unroll
        for (int kc = 0; kc < 2; kc++) {
            uint32_t af[4][4];
            #pragma unroll
            for (int mt = 0; mt < 4; mt++) {
                int row = wm * 64 + mt * 16 + arow_l;
                int col = kc * 8 + acol_l;
                ldmatrix_x4(af[mt], asmem + pb * ABUF + (row * SA + col) * 4);
            }
            #pragma unroll
            for (int nt = 0; nt < 8; nt++) {
                uint32_t bf[2];
                int c = wn * 64 + nt * 8 + g;
                int r = kc * 8 + tg;
                bf[0] = Bs[pb][r * SB + c];
                bf[1] = Bs[pb][(r + 4) * SB + c];
                #pragma unroll
                for (int mt = 0; mt < 4; mt++)
                    mma_tf32(acc[mt][nt], af[mt], bf);
            }
        }

        if (more) store_tile(pb ^ 1);
        __syncthreads();
        pb ^= 1;
    }

    // ---- epilogue ----
    #pragma unroll
    for (int mt = 0; mt < 4; mt++) {
        int mm = m0 + wm * 64 + mt * 16 + g;    // row (and mm+8)
        if (IS_QKV) {
            float* outBuf = (sel == 0 ? g_q : (sel == 1 ? g_k : g_v));
            int b = mm >> 11;
            int t = mm & 2047;
            int h = h0 + wn;
            #pragma unroll
            for (int nt = 0; nt < 8; nt++) {
                int d = nt * 8 + 2 * tg;
                float* o0 = &outBuf[((b * HH + h) * TT + t) * DD + d];
                float* o1 = &outBuf[((b * HH + h) * TT + t + 8) * DD + d];
                *(float2*)o0 = make_float2(acc[mt][nt][0], acc[mt][nt][1]);
                *(float2*)o1 = make_float2(acc[mt][nt][2], acc[mt][nt][3]);
            }
        } else {
            #pragma unroll
            for (int nt = 0; nt < 8; nt++) {
                int col = n0 + wn * 64 + nt * 8 + 2 * tg;
                float b0 = bp[col], b1 = bp[col + 1];
                *(float2*)&out[mm * CC + col] =
                    make_float2(acc[mt][nt][0] + b0, acc[mt][nt][1] + b1);
                *(float2*)&out[(mm + 8) * CC + col] =
                    make_float2(acc[mt][nt][2] + b0, acc[mt][nt][3] + b1);
            }
        }
    }
}

// ---------------------------------------------------------------------------
// Flash attention (causal) with tf32 tensor cores.
// Block: one (b,h), 64 queries, 4 warps (16 query rows each). Key tiles of 64.
// Q fragments (scale folded) register-resident. S = Q K^T via MMA; fragment
// online softmax; S C-fragments permuted to PV A-fragments via intra-quad
// shuffles (no SMEM round trip, no extra barrier).
// ---------------------------------------------------------------------------
#define SK 68   // Ks stride: 68 ≡ 4 (mod 32)
#define SV 72   // Vs stride: 72 ≡ 8 (mod 32)

__global__ __launch_bounds__(128, 3) void attn_tc()
{
    __shared__ uint32_t Ks[64 * SK];    // K tile; also used for Q staging
    __shared__ uint32_t Vs[64 * SV];    // V tile

    const int tid  = threadIdx.x;
    const int lane = tid & 31;
    const int warp = tid >> 5;          // 0..3
    const int g  = lane >> 2;
    const int tg = lane & 3;

    const int qt  = blockIdx.x;
    const int bh  = blockIdx.y;
    const int qt0 = qt * 64;

    // --- stage Q (pre-scaled by 1/8) into Ks, extract fragments ---
    {
        const float* qb = &g_q[(bh * TT + qt0) * DD];
        #pragma unroll
        for (int p = 0; p < 8; p++) {
            int idx = tid + p * 128;
            int r = idx >> 4, c4 = (idx & 15) * 4;
            float4 v = *(const float4*)&qb[r * DD + c4];
            uint4 w = make_uint4(f2tf(v.x * 0.125f), f2tf(v.y * 0.125f),
                                 f2tf(v.z * 0.125f), f2tf(v.w * 0.125f));
            *(uint4*)&Ks[r * SK + c4] = w;
        }
    }
    __syncthreads();
    uint32_t qa[8][4];
    #pragma unroll
    for (int kc = 0; kc < 8; kc++) {
        int r = warp * 16 + g, c = kc * 8 + tg;
        qa[kc][0] = Ks[r * SK + c];
        qa[kc][1] = Ks[(r + 8) * SK + c];
        qa[kc][2] = Ks[r * SK + c + 4];
        qa[kc][3] = Ks[(r + 8) * SK + c + 4];
    }

    float o[8][4] = {};
    float m0v = -1e30f, m1v = -1e30f, l0 = 0.f, l1 = 0.f;
    const int i0 = qt0 + warp * 16 + g;     // query row for c0/c1
    const int i1 = i0 + 8;                  // query row for c2/c3

    for (int jt = 0; jt <= qt; jt++) {
        __syncthreads();                    // prior iter's Ks/Vs reads done
        {
            const float* kb = &g_k[(bh * TT + jt * 64) * DD];
            const float* vb = &g_v[(bh * TT + jt * 64) * DD];
            #pragma unroll
            for (int p = 0; p < 8; p++) {
                int idx = tid + p * 128;
                int r = idx >> 4, c4 = (idx & 15) * 4;
                float4 kv = *(const float4*)&kb[r * DD + c4];
                float4 vv = *(const float4*)&vb[r * DD + c4];
                *(uint4*)&Ks[r * SK + c4] =
                    make_uint4(f2tf(kv.x), f2tf(kv.y), f2tf(kv.z), f2tf(kv.w));
                *(uint4*)&Vs[r * SV + c4] =
                    make_uint4(f2tf(vv.x), f2tf(vv.y), f2tf(vv.z), f2tf(vv.w));
            }
        }
        __syncthreads();

        // --- S = Q K^T (scale already in Q) ---
        float s[8][4] = {};
        #pragma unroll
        for (int kc = 0; kc < 8; kc++) {
            #pragma unroll
            for (int nt = 0; nt < 8; nt++) {
                uint32_t bf[2];
                int key = nt * 8 + g;
                int d   = kc * 8 + tg;
                bf[0] = Ks[key * SK + d];
                bf[1] = Ks[key * SK + d + 4];
                mma_tf32(s[nt], qa[kc], bf);
            }
        }

        // --- causal mask on diagonal tile ---
        if (jt == qt) {
            #pragma unroll
            for (int nt = 0; nt < 8; nt++) {
                int j = qt0 + nt * 8 + 2 * tg;
                if (j     > i0) s[nt][0] = -1e30f;
                if (j + 1 > i0) s[nt][1] = -1e30f;
                if (j     > i1) s[nt][2] = -1e30f;
                if (j + 1 > i1) s[nt][3] = -1e30f;
            }
        }

        // --- online softmax (rows i0, i1) ---
        float rmax0 = -1e30f, rmax1 = -1e30f;
        #pragma unroll
        for (int nt = 0; nt < 8; nt++) {
            rmax0 = fmaxf(rmax0, fmaxf(s[nt][0], s[nt][1]));
            rmax1 = fmaxf(rmax1, fmaxf(s[nt][2], s[nt][3]));
        }
        rmax0 = fmaxf(rmax0, __shfl_xor_sync(0xffffffffu, rmax0, 1));
        rmax0 = fmaxf(rmax0, __shfl_xor_sync(0xffffffffu, rmax0, 2));
        rmax1 = fmaxf(rmax1, __shfl_xor_sync(0xffffffffu, rmax1, 1));
        rmax1 = fmaxf(rmax1, __shfl_xor_sync(0xffffffffu, rmax1, 2));

        float mn0 = fmaxf(m0v, rmax0);
        float mn1 = fmaxf(m1v, rmax1);
        float al0 = __expf(m0v - mn0);
        float al1 = __expf(m1v - mn1);

        float ls0 = 0.f, ls1 = 0.f;
        #pragma unroll
        for (int nt = 0; nt < 8; nt++) {
            s[nt][0] = __expf(s[nt][0] - mn0);
            s[nt][1] = __expf(s[nt][1] - mn0);
            s[nt][2] = __expf(s[nt][2] - mn1);
            s[nt][3] = __expf(s[nt][3] - mn1);
            ls0 += s[nt][0] + s[nt][1];
            ls1 += s[nt][2] + s[nt][3];
        }
        ls0 += __shfl_xor_sync(0xffffffffu, ls0, 1);
        ls0 += __shfl_xor_sync(0xffffffffu, ls0, 2);
        ls1 += __shfl_xor_sync(0xffffffffu, ls1, 1);
        ls1 += __shfl_xor_sync(0xffffffffu, ls1, 2);

        l0 = l0 * al0 + ls0;  m0v = mn0;
        l1 = l1 * al1 + ls1;  m1v = mn1;

        #pragma unroll
        for (int nt = 0; nt < 8; nt++) {
            o[nt][0] *= al0; o[nt][1] *= al0;
            o[nt][2] *= al1; o[nt][3] *= al1;
        }

        // --- O += P V. Permute S C-frags -> A-frags via intra-quad shfl ---
        const int qbase = lane & ~3;
        const int srcA  = qbase + (tg >> 1);
        const int srcB  = srcA + 2;
        const bool odd  = tg & 1;
        #pragma unroll
        for (int kc = 0; kc < 8; kc++) {
            float c0 = s[kc][0], c1 = s[kc][1], c2 = s[kc][2], c3 = s[kc][3];
            float u0 = __shfl_sync(0xffffffffu, c0, srcA);
            float u1 = __shfl_sync(0xffffffffu, c1, srcA);
            float u2 = __shfl_sync(0xffffffffu, c2, srcA);
            float u3 = __shfl_sync(0xffffffffu, c3, srcA);
            float w0 = __shfl_sync(0xffffffffu, c0, srcB);
            float w1 = __shfl_sync(0xffffffffu, c1, srcB);
            float w2 = __shfl_sync(0xffffffffu, c2, srcB);
            float w3 = __shfl_sync(0xffffffffu, c3, srcB);
            uint32_t pa[4];
            pa[0] = f2tf(odd ? u1 : u0);    // P[g   ][kc*8+tg  ]
            pa[1] = f2tf(odd ? u3 : u2);    // P[g+8 ][kc*8+tg  ]
            pa[2] = f2tf(odd ? w1 : w0);    // P[g   ][kc*8+tg+4]
            pa[3] = f2tf(odd ? w3 : w2);    // P[g+8 ][kc*8+tg+4]
            #pragma unroll
            for (int nt = 0; nt < 8; nt++) {
                uint32_t vf[2];
                int key = kc * 8 + tg;
                int d   = nt * 8 + g;
                vf[0] = Vs[key * SV + d];
                vf[1] = Vs[(key + 4) * SV + d];
                mma_tf32(o[nt], pa, vf);
            }
        }
    }

    // --- normalize + store to [B,T,C] ---
    const float inv0 = 1.f / l0;
    const float inv1 = 1.f / l1;
    const int b = bh >> 4;
    const int h = bh & 15;
    const int r0 = qt0 + warp * 16 + g;
    float* ob0 = &g_att[(b * TT + r0) * CC + h * DD];
    float* ob1 = &g_att[(b * TT + r0 + 8) * CC + h * DD];
    #pragma unroll
    for (int nt = 0; nt < 8; nt++) {
        int col = nt * 8 + 2 * tg;
        *(float2*)&ob0[col] = make_float2(o[nt][0] * inv0, o[nt][1] * inv0);
        *(float2*)&ob1[col] = make_float2(o[nt][2] * inv1, o[nt][3] * inv1);
    }
}

// ---------------------------------------------------------------------------
extern "C" void kernel_launch(void* const* d_in, const int* in_sizes, int n_in,
                              void* d_out, int out_size)
{
    const float* x  = (const float*)d_in[0];
    const float* Wq = (const float*)d_in[1];
    const float* Wk = (const float*)d_in[2];
    const float* Wv = (const float*)d_in[3];
    const float* Wp = (const float*)d_in[4];
    const float* bp = (const float*)d_in[5];
    float* out = (float*)d_out;

    (void)in_sizes; (void)n_in; (void)out_size;

    // 1) fused QKV projections (tf32 MMA, 64x64 warp tiles): N=3072, M=4096
    gemm_tc<1><<<dim3(24, 32), 128>>>(x, Wq, Wk, Wv, nullptr, nullptr, nullptr);

    // 2) causal flash attention (tf32 MMA): 32 query tiles x 32 (b,h)
    attn_tc<<<dim3(32, 32), 128>>>();

    // 3) output projection + bias (tf32 MMA, 64x64 warp tiles): N=1024
    gemm_tc<0><<<dim3(8, 32), 128>>>(nullptr, nullptr, nullptr, nullptr, Wp, bp, out);
}

// round 7
// speedup vs baseline: 8.5325x; 1.5932x over previous
#include <cuda_runtime.h>
#include <cuda_fp16.h>
#include <cstdint>

// Problem constants
#define BB 2
#define TT 2048
#define CC 1024
#define HH 16
#define DD 64

// Scratch (static __device__ — no runtime allocation). fp16 intermediates.
__device__ __half g_q[BB*HH*TT*DD];     // [B,H,T,D]
__device__ __half g_k[BB*HH*TT*DD];
__device__ __half g_v[BB*HH*TT*DD];
__device__ __half g_att[BB*TT*CC];      // [B,T,C] (heads concatenated)

// ---------------------------------------------------------------------------
// fp16 MMA helpers
// ---------------------------------------------------------------------------
// D += A(16x16, f16, row) * B(16x8, f16, col); fp32 accumulate.
__device__ __forceinline__ void mma_f16(float* d, const uint32_t* a, const uint32_t* b) {
    asm volatile(
        "mma.sync.aligned.m16n8k16.row.col.f32.f16.f16.f32 "
        "{%0,%1,%2,%3}, {%4,%5,%6,%7}, {%8,%9}, {%0,%1,%2,%3};"
        : "+f"(d[0]), "+f"(d[1]), "+f"(d[2]), "+f"(d[3])
        : "r"(a[0]), "r"(a[1]), "r"(a[2]), "r"(a[3]),
          "r"(b[0]), "r"(b[1]));
}

__device__ __forceinline__ void ldm_x4(uint32_t* r, uint32_t addr) {
    asm volatile(
        "ldmatrix.sync.aligned.m8n8.x4.shared.b16 {%0,%1,%2,%3}, [%4];"
        : "=r"(r[0]), "=r"(r[1]), "=r"(r[2]), "=r"(r[3]) : "r"(addr));
}
__device__ __forceinline__ void ldm_x4_t(uint32_t* r, uint32_t addr) {
    asm volatile(
        "ldmatrix.sync.aligned.m8n8.x4.trans.shared.b16 {%0,%1,%2,%3}, [%4];"
        : "=r"(r[0]), "=r"(r[1]), "=r"(r[2]), "=r"(r[3]) : "r"(addr));
}

__device__ __forceinline__ uint32_t pack_h2(float a, float b) {
    __half2 h = __floats2half2_rn(a, b);
    return *(uint32_t*)&h;
}
__device__ __forceinline__ uint2 f4_to_h4(float4 v) {
    uint2 r;
    r.x = pack_h2(v.x, v.y);
    r.y = pack_h2(v.z, v.w);
    return r;
}

// SMEM strides in halves. SA_H rows: 80B stride -> ldmatrix row banks
// {0,20,8,28,16,4,24,12} (x4 words) conflict-free. SB_H rows: 272B -> 4i.
#define SA_H 40    // A tile: 128 x 16 halves
#define SB_H 136   // B tile: 16 x 128 halves

// ---------------------------------------------------------------------------
// Shared GEMM body (fp16 MMA, double-buffered, ldmatrix both operands).
// BM=128, BN=128, BK=16. 128 threads = 4 warps; warp tile 64(m) x 64(n).
// IS_QKV=1: A = x (fp32), B = per-head W (fp32), out -> g_q/k/v (half).
// IS_QKV=0: A = g_att (half), B = Wp (fp32), out = d_out (fp32) + bias.
// ---------------------------------------------------------------------------
template<int IS_QKV>
__global__ __launch_bounds__(128, 2) void gemm_tc(
    const float* __restrict__ Ain,
    const float* __restrict__ Wq,
    const float* __restrict__ Wk,
    const float* __restrict__ Wv,
    const float* __restrict__ Wp,
    const float* __restrict__ bp,
    float* __restrict__ out)
{
    __shared__ __half As[2][128 * SA_H];   // 2 x 10.0 KB
    __shared__ __half Bs[2][16 * SB_H];    // 2 x 4.25 KB

    const int tid  = threadIdx.x;
    const int lane = tid & 31;
    const int warp = tid >> 5;          // 0..3
    const int wm = warp & 1;            // m strip of 64 rows
    const int wn = warp >> 1;           // n strip of 64 cols
    const int g  = lane >> 2;
    const int tg = lane & 3;

    const int m0 = blockIdx.y * 128;
    const int n0 = blockIdx.x * 128;

    // B source resolution
    const float* W;
    int h0 = 0, sel = 0;
    if (IS_QKV) {
        sel = n0 >> 10;                 // 0=q,1=k,2=v
        h0  = (n0 & 1023) >> 6;         // first of two heads in this tile
        W   = (sel == 0 ? Wq : (sel == 1 ? Wk : Wv));
    } else {
        W = Wp;
    }

    // Load-index mapping
    const int a_r  = tid >> 2;              // qkv A: base row (4 passes of 32)
    const int a_c4 = (tid & 3) * 4;
    const int b_r  = tid >> 5;              // B: base k-row (4 passes of 4)
    const int b_c4 = (tid & 31) * 4;

    // ldmatrix lane addressing (A-style; also valid for trans-B)
    const int lrow  = (lane & 7) + ((lane >> 3) & 1) * 8;
    const int lcol8 = ((lane >> 4) & 1) * 8;
    const uint32_t a_base = (uint32_t)__cvta_generic_to_shared(&As[0][0]);
    const uint32_t b_base = (uint32_t)__cvta_generic_to_shared(&Bs[0][0]);
    const uint32_t ABUF = 128 * SA_H * 2;
    const uint32_t BBUF = 16 * SB_H * 2;

    float4 av[4];      // qkv A staging (fp32 source)
    uint4  avh[2];     // proj A staging (half source)
    float4 bv[4];      // B staging (fp32 source)

    auto load_tile = [&](int k0) {
        if (IS_QKV) {
            #pragma unroll
            for (int p = 0; p < 4; p++) {
                int r = a_r + p * 32;
                av[p] = *(const float4*)&Ain[(m0 + r) * CC + k0 + a_c4];
            }
        } else {
            #pragma unroll
            for (int p = 0; p < 2; p++) {
                int idx = tid + p * 128;
                int r = idx >> 1, c8 = (idx & 1) * 8;
                avh[p] = *(const uint4*)&g_att[(m0 + r) * CC + k0 + c8];
            }
        }
        #pragma unroll
        for (int p = 0; p < 4; p++) {
            int r = b_r + p * 4;
            if (IS_QKV) {
                int h = h0 + (b_c4 >> 6);
                int d = b_c4 & 63;
                bv[p] = *(const float4*)&W[(h * CC + (k0 + r)) * DD + d];
            } else {
                bv[p] = *(const float4*)&W[(k0 + r) * CC + n0 + b_c4];
            }
        }
    };
    auto store_tile = [&](int buf) {
        if (IS_QKV) {
            #pragma unroll
            for (int p = 0; p < 4; p++) {
                int r = a_r + p * 32;
                *(uint2*)&As[buf][r * SA_H + a_c4] = f4_to_h4(av[p]);
            }
        } else {
            #pragma unroll
            for (int p = 0; p < 2; p++) {
                int idx = tid + p * 128;
                int r = idx >> 1, c8 = (idx & 1) * 8;
                *(uint4*)&As[buf][r * SA_H + c8] = avh[p];
            }
        }
        #pragma unroll
        for (int p = 0; p < 4; p++) {
            int r = b_r + p * 4;
            *(uint2*)&Bs[buf][r * SB_H + b_c4] = f4_to_h4(bv[p]);
        }
    };

    float acc[4][8][4] = {};            // [mt][nt][4]

    load_tile(0);
    store_tile(0);
    __syncthreads();

    int pb = 0;
    for (int k0 = 0; k0 < CC; k0 += 16) {
        const bool more = (k0 + 16) < CC;
        if (more) load_tile(k0 + 16);

        // A fragments: 4 x ldmatrix.x4 (m16k16 each)
        uint32_t af[4][4];
        #pragma unroll
        for (int mt = 0; mt < 4; mt++) {
            int row = wm * 64 + mt * 16 + lrow;
            ldm_x4(af[mt], a_base + pb * ABUF + (row * SA_H + lcol8) * 2);
        }
        // B fragments: 4 x ldmatrix.x4.trans, each covers 2 n-strips of 8
        uint32_t bf[4][4];
        #pragma unroll
        for (int np = 0; np < 4; np++) {
            int col = wn * 64 + np * 16 + lcol8;
            ldm_x4_t(bf[np], b_base + pb * BBUF + (lrow * SB_H + col) * 2);
        }
        #pragma unroll
        for (int nt = 0; nt < 8; nt++) {
            const uint32_t* bb = &bf[nt >> 1][(nt & 1) * 2];
            #pragma unroll
            for (int mt = 0; mt < 4; mt++)
                mma_f16(acc[mt][nt], af[mt], bb);
        }

        if (more) store_tile(pb ^ 1);
        __syncthreads();
        pb ^= 1;
    }

    // ---- epilogue ----
    #pragma unroll
    for (int mt = 0; mt < 4; mt++) {
        int mm = m0 + wm * 64 + mt * 16 + g;    // row (and mm+8)
        if (IS_QKV) {
            __half* outBuf = (sel == 0 ? g_q : (sel == 1 ? g_k : g_v));
            int b = mm >> 11;
            int t = mm & 2047;
            int h = h0 + wn;
            #pragma unroll
            for (int nt = 0; nt < 8; nt++) {
                int d = nt * 8 + 2 * tg;
                *(uint32_t*)&outBuf[((b * HH + h) * TT + t) * DD + d] =
                    pack_h2(acc[mt][nt][0], acc[mt][nt][1]);
                *(uint32_t*)&outBuf[((b * HH + h) * TT + t + 8) * DD + d] =
                    pack_h2(acc[mt][nt][2], acc[mt][nt][3]);
            }
        } else {
            #pragma unroll
            for (int nt = 0; nt < 8; nt++) {
                int col = n0 + wn * 64 + nt * 8 + 2 * tg;
                float b0 = bp[col], b1 = bp[col + 1];
                *(float2*)&out[mm * CC + col] =
                    make_float2(acc[mt][nt][0] + b0, acc[mt][nt][1] + b1);
                *(float2*)&out[(mm + 8) * CC + col] =
                    make_float2(acc[mt][nt][2] + b0, acc[mt][nt][3] + b1);
            }
        }
    }
}

// ---------------------------------------------------------------------------
// Flash attention (causal), fp16 MMA.
// Block: one (b,h), 64 queries, 4 warps (16 query rows each). Key tiles of 64.
// Q A-frags register-resident (scale folded). S = Q K^T with K-frags via
// non-trans ldmatrix; online softmax in fp32; P packs directly into the PV
// A-fragment (k-pairs == C-frag column pairs -> no shuffles); V via
// ldmatrix.trans.
// ---------------------------------------------------------------------------
#define SKH 72   // 144B rows -> ldmatrix banks 4i, conflict-free
#define SVH 72

__global__ __launch_bounds__(128, 3) void attn_tc()
{
    __shared__ __half Ks[64 * SKH];     // K tile; also Q staging
    __shared__ __half Vs[64 * SVH];     // V tile

    const int tid  = threadIdx.x;
    const int lane = tid & 31;
    const int warp = tid >> 5;          // 0..3
    const int g  = lane >> 2;
    const int tg = lane & 3;

    const int qt  = blockIdx.x;
    const int bh  = blockIdx.y;
    const int qt0 = qt * 64;

    const uint32_t ks_base = (uint32_t)__cvta_generic_to_shared(&Ks[0]);
    const uint32_t vs_base = (uint32_t)__cvta_generic_to_shared(&Vs[0]);
    // A-style lane map (A-frags, trans-B V-frags)
    const int lrowA  = (lane & 7) + ((lane >> 3) & 1) * 8;
    const int lcol8A = ((lane >> 4) & 1) * 8;
    // K-style lane map (non-trans B-frags: bit3 -> d+8, bit4 -> key+8)
    const int lrowK  = (lane & 7) + ((lane >> 4) & 1) * 8;
    const int lcol8K = ((lane >> 3) & 1) * 8;

    // --- stage Q (pre-scaled by 1/8) into Ks, extract A-fragments ---
    {
        const __half* qb = &g_q[(bh * TT + qt0) * DD];
        const __half2 sc2 = __floats2half2_rn(0.125f, 0.125f);
        #pragma unroll
        for (int p = 0; p < 4; p++) {
            int idx = tid + p * 128;
            int r = idx >> 3, c8 = (idx & 7) * 8;
            uint4 v = *(const uint4*)&qb[r * DD + c8];
            __half2* hp = (__half2*)&v;
            #pragma unroll
            for (int i = 0; i < 4; i++) hp[i] = __hmul2(hp[i], sc2);
            *(uint4*)&Ks[r * SKH + c8] = v;
        }
    }
    __syncthreads();
    uint32_t qa[4][4];                  // 4 k16-chunks over D=64
    #pragma unroll
    for (int kc = 0; kc < 4; kc++) {
        int row = warp * 16 + lrowA;
        ldm_x4(qa[kc], ks_base + (row * SKH + kc * 16 + lcol8A) * 2);
    }

    float o[8][4] = {};
    float m0v = -1e30f, m1v = -1e30f, l0 = 0.f, l1 = 0.f;
    const int i0 = qt0 + warp * 16 + g;     // query row for c0/c1
    const int i1 = i0 + 8;                  // query row for c2/c3

    for (int jt = 0; jt <= qt; jt++) {
        __syncthreads();                    // prior iter's Ks/Vs reads done
        {
            const __half* kb = &g_k[(bh * TT + jt * 64) * DD];
            const __half* vb = &g_v[(bh * TT + jt * 64) * DD];
            #pragma unroll
            for (int p = 0; p < 4; p++) {
                int idx = tid + p * 128;
                int r = idx >> 3, c8 = (idx & 7) * 8;
                *(uint4*)&Ks[r * SKH + c8] = *(const uint4*)&kb[r * DD + c8];
                *(uint4*)&Vs[r * SVH + c8] = *(const uint4*)&vb[r * DD + c8];
            }
        }
        __syncthreads();

        // --- S = Q K^T (scale folded into Q) ---
        float s[8][4] = {};
        #pragma unroll
        for (int kc = 0; kc < 4; kc++) {
            uint32_t kf[4][4];
            #pragma unroll
            for (int np = 0; np < 4; np++) {
                int key = np * 16 + lrowK;
                ldm_x4(kf[np], ks_base + (key * SKH + kc * 16 + lcol8K) * 2);
            }
            #pragma unroll
            for (int nt = 0; nt < 8; nt++)
                mma_f16(s[nt], qa[kc], &kf[nt >> 1][(nt & 1) * 2]);
        }

        // --- causal mask on diagonal tile ---
        if (jt == qt) {
            #pragma unroll
            for (int nt = 0; nt < 8; nt++) {
                int j = qt0 + nt * 8 + 2 * tg;
                if (j     > i0) s[nt][0] = -1e30f;
                if (j + 1 > i0) s[nt][1] = -1e30f;
                if (j     > i1) s[nt][2] = -1e30f;
                if (j + 1 > i1) s[nt][3] = -1e30f;
            }
        }

        // --- online softmax (rows i0, i1), fp32 ---
        float rmax0 = -1e30f, rmax1 = -1e30f;
        #pragma unroll
        for (int nt = 0; nt < 8; nt++) {
            rmax0 = fmaxf(rmax0, fmaxf(s[nt][0], s[nt][1]));
            rmax1 = fmaxf(rmax1, fmaxf(s[nt][2], s[nt][3]));
        }
        rmax0 = fmaxf(rmax0, __shfl_xor_sync(0xffffffffu, rmax0, 1));
        rmax0 = fmaxf(rmax0, __shfl_xor_sync(0xffffffffu, rmax0, 2));
        rmax1 = fmaxf(rmax1, __shfl_xor_sync(0xffffffffu, rmax1, 1));
        rmax1 = fmaxf(rmax1, __shfl_xor_sync(0xffffffffu, rmax1, 2));

        float mn0 = fmaxf(m0v, rmax0);
        float mn1 = fmaxf(m1v, rmax1);
        float al0 = __expf(m0v - mn0);
        float al1 = __expf(m1v - mn1);

        float ls0 = 0.f, ls1 = 0.f;
        #pragma unroll
        for (int nt = 0; nt < 8; nt++) {
            s[nt][0] = __expf(s[nt][0] - mn0);
            s[nt][1] = __expf(s[nt][1] - mn0);
            s[nt][2] = __expf(s[nt][2] - mn1);
            s[nt][3] = __expf(s[nt][3] - mn1);
            ls0 += s[nt][0] + s[nt][1];
            ls1 += s[nt][2] + s[nt][3];
        }
        ls0 += __shfl_xor_sync(0xffffffffu, ls0, 1);
        ls0 += __shfl_xor_sync(0xffffffffu, ls0, 2);
        ls1 += __shfl_xor_sync(0xffffffffu, ls1, 1);
        ls1 += __shfl_xor_sync(0xffffffffu, ls1, 2);

        l0 = l0 * al0 + ls0;  m0v = mn0;
        l1 = l1 * al1 + ls1;  m1v = mn1;

        #pragma unroll
        for (int nt = 0; nt < 8; nt++) {
            o[nt][0] *= al0; o[nt][1] *= al0;
            o[nt][2] *= al1; o[nt][3] *= al1;
        }

        // --- O += P V. A-frag k-pairs == C-frag column pairs: direct pack ---
        #pragma unroll
        for (int kc = 0; kc < 4; kc++) {
            uint32_t pa[4];
            pa[0] = pack_h2(s[2*kc  ][0], s[2*kc  ][1]);
            pa[1] = pack_h2(s[2*kc  ][2], s[2*kc  ][3]);
            pa[2] = pack_h2(s[2*kc+1][0], s[2*kc+1][1]);
            pa[3] = pack_h2(s[2*kc+1][2], s[2*kc+1][3]);
            uint32_t vf[4][4];
            #pragma unroll
            for (int np = 0; np < 4; np++) {
                int key = kc * 16 + lrowA;
                ldm_x4_t(vf[np], vs_base + (key * SVH + np * 16 + lcol8A) * 2);
            }
            #pragma unroll
            for (int nt = 0; nt < 8; nt++)
                mma_f16(o[nt], pa, &vf[nt >> 1][(nt & 1) * 2]);
        }
    }

    // --- normalize + store to g_att [B,T,C] (half) ---
    const float inv0 = 1.f / l0;
    const float inv1 = 1.f / l1;
    const int b = bh >> 4;
    const int h = bh & 15;
    const int r0 = qt0 + warp * 16 + g;
    __half* ob0 = &g_att[(b * TT + r0) * CC + h * DD];
    __half* ob1 = &g_att[(b * TT + r0 + 8) * CC + h * DD];
    #pragma unroll
    for (int nt = 0; nt < 8; nt++) {
        int col = nt * 8 + 2 * tg;
        *(uint32_t*)&ob0[col] = pack_h2(o[nt][0] * inv0, o[nt][1] * inv0);
        *(uint32_t*)&ob1[col] = pack_h2(o[nt][2] * inv1, o[nt][3] * inv1);
    }
}

// ---------------------------------------------------------------------------
extern "C" void kernel_launch(void* const* d_in, const int* in_sizes, int n_in,
                              void* d_out, int out_size)
{
    const float* x  = (const float*)d_in[0];
    const float* Wq = (const float*)d_in[1];
    const float* Wk = (const float*)d_in[2];
    const float* Wv = (const float*)d_in[3];
    const float* Wp = (const float*)d_in[4];
    const float* bp = (const float*)d_in[5];
    float* out = (float*)d_out;

    (void)in_sizes; (void)n_in; (void)out_size;

    // 1) fused QKV projections (fp16 MMA): N=3072, M=4096
    gemm_tc<1><<<dim3(24, 32), 128>>>(x, Wq, Wk, Wv, nullptr, nullptr, nullptr);

    // 2) causal flash attention (fp16 MMA): 32 query tiles x 32 (b,h)
    attn_tc<<<dim3(32, 32), 128>>>();

    // 3) output projection + bias (fp16 MMA): N=1024
    gemm_tc<0><<<dim3(8, 32), 128>>>(nullptr, nullptr, nullptr, nullptr, Wp, bp, out);
}

// round 9
// speedup vs baseline: 8.8828x; 1.0411x over previous
#include <cuda_runtime.h>
#include <cuda_fp16.h>
#include <cstdint>

// Problem constants
#define BB 2
#define TT 2048
#define CC 1024
#define HH 16
#define DD 64
#define MM (BB*TT)

// Scratch (static __device__ — no runtime allocation). fp16 everywhere.
__device__ __half g_xh[MM*CC];          // x converted
__device__ __half g_wqh[HH*CC*DD];      // Wq converted
__device__ __half g_wkh[HH*CC*DD];
__device__ __half g_wvh[HH*CC*DD];
__device__ __half g_wph[CC*CC];         // Wp converted
__device__ __half g_q[BB*HH*TT*DD];     // [B,H,T,D]
__device__ __half g_k[BB*HH*TT*DD];
__device__ __half g_v[BB*HH*TT*DD];
__device__ __half g_att[BB*TT*CC];      // [B,T,C]

// ---------------------------------------------------------------------------
// helpers
// ---------------------------------------------------------------------------
__device__ __forceinline__ void mma_f16(float* d, const uint32_t* a, const uint32_t* b) {
    asm volatile(
        "mma.sync.aligned.m16n8k16.row.col.f32.f16.f16.f32 "
        "{%0,%1,%2,%3}, {%4,%5,%6,%7}, {%8,%9}, {%0,%1,%2,%3};"
        : "+f"(d[0]), "+f"(d[1]), "+f"(d[2]), "+f"(d[3])
        : "r"(a[0]), "r"(a[1]), "r"(a[2]), "r"(a[3]),
          "r"(b[0]), "r"(b[1]));
}
__device__ __forceinline__ void ldm_x4(uint32_t* r, uint32_t addr) {
    asm volatile(
        "ldmatrix.sync.aligned.m8n8.x4.shared.b16 {%0,%1,%2,%3}, [%4];"
        : "=r"(r[0]), "=r"(r[1]), "=r"(r[2]), "=r"(r[3]) : "r"(addr));
}
__device__ __forceinline__ void ldm_x4_t(uint32_t* r, uint32_t addr) {
    asm volatile(
        "ldmatrix.sync.aligned.m8n8.x4.trans.shared.b16 {%0,%1,%2,%3}, [%4];"
        : "=r"(r[0]), "=r"(r[1]), "=r"(r[2]), "=r"(r[3]) : "r"(addr));
}
__device__ __forceinline__ uint32_t pack_h2(float a, float b) {
    __half2 h = __floats2half2_rn(a, b);
    return *(uint32_t*)&h;
}
__device__ __forceinline__ void cp16(uint32_t dst, const void* src) {
    asm volatile("cp.async.cg.shared.global [%0], [%1], 16;" :: "r"(dst), "l"(src));
}
__device__ __forceinline__ void cp_commit() {
    asm volatile("cp.async.commit_group;");
}
template<int N> __device__ __forceinline__ void cp_wait() {
    asm volatile("cp.async.wait_group %0;" :: "n"(N));
}

// ---------------------------------------------------------------------------
// fp32 -> fp16 conversion pre-pass (grid-stride, float4 -> half4)
// ---------------------------------------------------------------------------
__global__ void cvt_kernel(const float4* __restrict__ src, uint2* __restrict__ dst, int n4)
{
    int i = blockIdx.x * blockDim.x + threadIdx.x;
    int stride = gridDim.x * blockDim.x;
    for (; i < n4; i += stride) {
        float4 v = src[i];
        uint2 r;
        r.x = pack_h2(v.x, v.y);
        r.y = pack_h2(v.z, v.w);
        dst[i] = r;
    }
}

// SMEM strides (halves). SA_H=40 (80B rows, 16B-aligned; ldmatrix banks
// 20r mod 32 = {0,20,8,28,16,4,24,12} conflict-free). SB_H=136 (272B rows,
// banks 4r pattern conflict-free).
#define SA_H 40    // A tile: 128 x 32 halves
#define SB_H 136   // B tile: 32 x 128 halves

// ---------------------------------------------------------------------------
// GEMM (fp16 MMA, cp.async double-buffered, BK=32).
// BM=128, BN=128. 128 threads = 4 warps; warp tile 64(m) x 64(n).
// IS_QKV=1: A=g_xh, B=g_w{q,k,v}h (two heads per N tile), out -> g_q/k/v.
// IS_QKV=0: A=g_att, B=g_wph, out=d_out (fp32) + bias.
// ---------------------------------------------------------------------------
template<int IS_QKV>
__global__ __launch_bounds__(128, 2) void gemm_tc(
    const float* __restrict__ bp,
    float* __restrict__ out)
{
    __shared__ __half As[2][128 * SA_H];   // 2 x 10.0 KB
    __shared__ __half Bs[2][32 * SB_H];    // 2 x 8.5 KB

    const int tid  = threadIdx.x;
    const int lane = tid & 31;
    const int warp = tid >> 5;
    const int wm = warp & 1;
    const int wn = warp >> 1;
    const int g  = lane >> 2;
    const int tg = lane & 3;

    const int m0 = blockIdx.y * 128;
    const int n0 = blockIdx.x * 128;

    const __half* A = IS_QKV ? g_xh : g_att;
    const __half* W;
    int h0 = 0, sel = 0;
    if (IS_QKV) {
        sel = n0 >> 10;
        h0  = (n0 & 1023) >> 6;
        W   = (sel == 0 ? g_wqh : (sel == 1 ? g_wkh : g_wvh));
    } else {
        W = g_wph;
    }

    // cp.async index mapping (16B = 8 halves per op, 4 passes each)
    const int a_r  = tid >> 2;              // 0..31 base
    const int a_c8 = (tid & 3) * 8;
    const int b_r  = tid >> 4;              // 0..7 base
    const int b_c8 = (tid & 15) * 8;

    // ldmatrix lane maps
    const int lrow  = (lane & 7) + ((lane >> 3) & 1) * 8;
    const int lcol8 = ((lane >> 4) & 1) * 8;
    const uint32_t a_base = (uint32_t)__cvta_generic_to_shared(&As[0][0]);
    const uint32_t b_base = (uint32_t)__cvta_generic_to_shared(&Bs[0][0]);
    const uint32_t ABUF = 128 * SA_H * 2;
    const uint32_t BBUF = 32 * SB_H * 2;

    auto load_tile = [&](int k0, int buf) {
        #pragma unroll
        for (int p = 0; p < 4; p++) {
            int r = a_r + p * 32;           // 0..127
            cp16(a_base + buf * ABUF + (r * SA_H + a_c8) * 2,
                 &A[(m0 + r) * CC + k0 + a_c8]);
        }
        #pragma unroll
        for (int p = 0; p < 4; p++) {
            int r = b_r + p * 8;            // 0..31 (k-row)
            const __half* src;
            if (IS_QKV) {
                int h = h0 + (b_c8 >> 6);
                int d = b_c8 & 63;
                src = &W[(h * CC + (k0 + r)) * DD + d];
            } else {
                src = &W[(k0 + r) * CC + n0 + b_c8];
            }
            cp16(b_base + buf * BBUF + (r * SB_H + b_c8) * 2, src);
        }
    };

    float acc[4][8][4] = {};

    load_tile(0, 0);
    cp_commit();

    int pb = 0;
    for (int k0 = 0; k0 < CC; k0 += 32) {
        const bool more = (k0 + 32) < CC;
        if (more) {
            load_tile(k0 + 32, pb ^ 1);
            cp_commit();
            cp_wait<1>();
        } else {
            cp_wait<0>();
        }
        __syncthreads();

        #pragma unroll
        for (int kc = 0; kc < 2; kc++) {
            uint32_t af[4][4];
            #pragma unroll
            for (int mt = 0; mt < 4; mt++) {
                int row = wm * 64 + mt * 16 + lrow;
                ldm_x4(af[mt], a_base + pb * ABUF + (row * SA_H + kc * 16 + lcol8) * 2);
            }
            uint32_t bf[4][4];
            #pragma unroll
            for (int np = 0; np < 4; np++) {
                int col = wn * 64 + np * 16 + lcol8;
                ldm_x4_t(bf[np], b_base + pb * BBUF + ((kc * 16 + lrow) * SB_H + col) * 2);
            }
            #pragma unroll
            for (int nt = 0; nt < 8; nt++) {
                const uint32_t* bb = &bf[nt >> 1][(nt & 1) * 2];
                #pragma unroll
                for (int mt = 0; mt < 4; mt++)
                    mma_f16(acc[mt][nt], af[mt], bb);
            }
        }

        __syncthreads();        // all reads of pb done before it's reloaded
        pb ^= 1;
    }

    // ---- epilogue ----
    #pragma unroll
    for (int mt = 0; mt < 4; mt++) {
        int mm = m0 + wm * 64 + mt * 16 + g;
        if (IS_QKV) {
            __half* outBuf = (sel == 0 ? g_q : (sel == 1 ? g_k : g_v));
            int b = mm >> 11;
            int t = mm & 2047;
            int h = h0 + wn;
            #pragma unroll
            for (int nt = 0; nt < 8; nt++) {
                int d = nt * 8 + 2 * tg;
                *(uint32_t*)&outBuf[((b * HH + h) * TT + t) * DD + d] =
                    pack_h2(acc[mt][nt][0], acc[mt][nt][1]);
                *(uint32_t*)&outBuf[((b * HH + h) * TT + t + 8) * DD + d] =
                    pack_h2(acc[mt][nt][2], acc[mt][nt][3]);
            }
        } else {
            #pragma unroll
            for (int nt = 0; nt < 8; nt++) {
                int col = n0 + wn * 64 + nt * 8 + 2 * tg;
                float b0 = bp[col], b1 = bp[col + 1];
                *(float2*)&out[mm * CC + col] =
                    make_float2(acc[mt][nt][0] + b0, acc[mt][nt][1] + b1);
                *(float2*)&out[(mm + 8) * CC + col] =
                    make_float2(acc[mt][nt][2] + b0, acc[mt][nt][3] + b1);
            }
        }
    }
}

// ---------------------------------------------------------------------------
// Flash attention (causal), fp16 MMA, cp.async double-buffered K/V.
// Block: one (b,h), 64 queries, 4 warps. Key tiles of 64, prefetch jt+1.
// ---------------------------------------------------------------------------
#define SKH 72   // 144B rows; banks 4r conflict-free
#define SVH 72

__global__ __launch_bounds__(128, 3) void attn_tc()
{
    __shared__ __half Ks[2][64 * SKH];
    __shared__ __half Vs[2][64 * SVH];

    const int tid  = threadIdx.x;
    const int lane = tid & 31;
    const int warp = tid >> 5;
    const int g  = lane >> 2;
    const int tg = lane & 3;

    const int qt  = blockIdx.x;
    const int bh  = blockIdx.y;
    const int qt0 = qt * 64;

    const uint32_t ks_base = (uint32_t)__cvta_generic_to_shared(&Ks[0][0]);
    const uint32_t vs_base = (uint32_t)__cvta_generic_to_shared(&Vs[0][0]);
    const uint32_t KBUF = 64 * SKH * 2;
    const uint32_t VBUF = 64 * SVH * 2;
    const int lrowA  = (lane & 7) + ((lane >> 3) & 1) * 8;
    const int lcol8A = ((lane >> 4) & 1) * 8;
    const int lrowK  = (lane & 7) + ((lane >> 4) & 1) * 8;
    const int lcol8K = ((lane >> 3) & 1) * 8;

    // cp.async mapping for 64x64-half tiles (4 passes)
    const int t_r  = tid >> 1;              // 0..63
    const int t_c8 = (tid & 1) * 8;         // + pass offsets

    auto load_kv = [&](int jt, int buf) {
        const __half* kb = &g_k[(bh * TT + jt * 64) * DD];
        const __half* vb = &g_v[(bh * TT + jt * 64) * DD];
        #pragma unroll
        for (int p = 0; p < 4; p++) {
            int c8 = t_c8 + (p & 1) * 16 + (p >> 1) * 32;
            cp16(ks_base + buf * KBUF + (t_r * SKH + c8) * 2, &kb[t_r * DD + c8]);
            cp16(vs_base + buf * VBUF + (t_r * SVH + c8) * 2, &vb[t_r * DD + c8]);
        }
    };

    // --- stage Q (scaled 1/8) into Ks[0], extract A-frags ---
    {
        const __half* qb = &g_q[(bh * TT + qt0) * DD];
        const __half2 sc2 = __floats2half2_rn(0.125f, 0.125f);
        #pragma unroll
        for (int p = 0; p < 4; p++) {
            int idx = tid + p * 128;
            int r = idx >> 3, c8 = (idx & 7) * 8;
            uint4 v = *(const uint4*)&qb[r * DD + c8];
            __half2* hp = (__half2*)&v;
            #pragma unroll
            for (int i = 0; i < 4; i++) hp[i] = __hmul2(hp[i], sc2);
            *(uint4*)&Ks[0][r * SKH + c8] = v;
        }
    }
    __syncthreads();
    uint32_t qa[4][4];
    #pragma unroll
    for (int kc = 0; kc < 4; kc++) {
        int row = warp * 16 + lrowA;
        ldm_x4(qa[kc], ks_base + (row * SKH + kc * 16 + lcol8A) * 2);
    }
    __syncthreads();            // Q reads done before Ks[0] reused for K

    load_kv(0, 0);
    cp_commit();

    float o[8][4] = {};
    float m0v = -1e30f, m1v = -1e30f, l0 = 0.f, l1 = 0.f;
    const int i0 = qt0 + warp * 16 + g;
    const int i1 = i0 + 8;

    int pb = 0;
    for (int jt = 0; jt <= qt; jt++) {
        const bool more = jt < qt;
        if (more) {
            load_kv(jt + 1, pb ^ 1);
            cp_commit();
            cp_wait<1>();
        } else {
            cp_wait<0>();
        }
        __syncthreads();

        // --- S = Q K^T ---
        float s[8][4] = {};
        #pragma unroll
        for (int kc = 0; kc < 4; kc++) {
            uint32_t kf[4][4];
            #pragma unroll
            for (int np = 0; np < 4; np++) {
                int key = np * 16 + lrowK;
                ldm_x4(kf[np], ks_base + pb * KBUF + (key * SKH + kc * 16 + lcol8K) * 2);
            }
            #pragma unroll
            for (int nt = 0; nt < 8; nt++)
                mma_f16(s[nt], qa[kc], &kf[nt >> 1][(nt & 1) * 2]);
        }

        if (jt == qt) {
            #pragma unroll
            for (int nt = 0; nt < 8; nt++) {
                int j = qt0 + nt * 8 + 2 * tg;
                if (j     > i0) s[nt][0] = -1e30f;
                if (j + 1 > i0) s[nt][1] = -1e30f;
                if (j     > i1) s[nt][2] = -1e30f;
                if (j + 1 > i1) s[nt][3] = -1e30f;
            }
        }

        // --- online softmax ---
        float rmax0 = -1e30f, rmax1 = -1e30f;
        #pragma unroll
        for (int nt = 0; nt < 8; nt++) {
            rmax0 = fmaxf(rmax0, fmaxf(s[nt][0], s[nt][1]));
            rmax1 = fmaxf(rmax1, fmaxf(s[nt][2], s[nt][3]));
        }
        rmax0 = fmaxf(rmax0, __shfl_xor_sync(0xffffffffu, rmax0, 1));
        rmax0 = fmaxf(rmax0, __shfl_xor_sync(0xffffffffu, rmax0, 2));
        rmax1 = fmaxf(rmax1, __shfl_xor_sync(0xffffffffu, rmax1, 1));
        rmax1 = fmaxf(rmax1, __shfl_xor_sync(0xffffffffu, rmax1, 2));

        float mn0 = fmaxf(m0v, rmax0);
        float mn1 = fmaxf(m1v, rmax1);
        float al0 = __expf(m0v - mn0);
        float al1 = __expf(m1v - mn1);

        float ls0 = 0.f, ls1 = 0.f;
        #pragma unroll
        for (int nt = 0; nt < 8; nt++) {
            s[nt][0] = __expf(s[nt][0] - mn0);
            s[nt][1] = __expf(s[nt][1] - mn0);
            s[nt][2] = __expf(s[nt][2] - mn1);
            s[nt][3] = __expf(s[nt][3] - mn1);
            ls0 += s[nt][0] + s[nt][1];
            ls1 += s[nt][2] + s[nt][3];
        }
        ls0 += __shfl_xor_sync(0xffffffffu, ls0, 1);
        ls0 += __shfl_xor_sync(0xffffffffu, ls0, 2);
        ls1 += __shfl_xor_sync(0xffffffffu, ls1, 1);
        ls1 += __shfl_xor_sync(0xffffffffu, ls1, 2);

        l0 = l0 * al0 + ls0;  m0v = mn0;
        l1 = l1 * al1 + ls1;  m1v = mn1;

        #pragma unroll
        for (int nt = 0; nt < 8; nt++) {
            o[nt][0] *= al0; o[nt][1] *= al0;
            o[nt][2] *= al1; o[nt][3] *= al1;
        }

        // --- O += P V (direct pack of S into A-frags) ---
        #pragma unroll
        for (int kc = 0; kc < 4; kc++) {
            uint32_t pa[4];
            pa[0] = pack_h2(s[2*kc  ][0], s[2*kc  ][1]);
            pa[1] = pack_h2(s[2*kc  ][2], s[2*kc  ][3]);
            pa[2] = pack_h2(s[2*kc+1][0], s[2*kc+1][1]);
            pa[3] = pack_h2(s[2*kc+1][2], s[2*kc+1][3]);
            uint32_t vf[4][4];
            #pragma unroll
            for (int np = 0; np < 4; np++) {
                int key = kc * 16 + lrowA;
                ldm_x4_t(vf[np], vs_base + pb * VBUF + (key * SVH + np * 16 + lcol8A) * 2);
            }
            #pragma unroll
            for (int nt = 0; nt < 8; nt++)
                mma_f16(o[nt], pa, &vf[nt >> 1][(nt & 1) * 2]);
        }

        __syncthreads();        // reads of pb done before it's reloaded
        pb ^= 1;
    }

    // --- normalize + store to g_att ---
    const float inv0 = 1.f / l0;
    const float inv1 = 1.f / l1;
    const int b = bh >> 4;
    const int h = bh & 15;
    const int r0 = qt0 + warp * 16 + g;
    __half* ob0 = &g_att[(b * TT + r0) * CC + h * DD];
    __half* ob1 = &g_att[(b * TT + r0 + 8) * CC + h * DD];
    #pragma unroll
    for (int nt = 0; nt < 8; nt++) {
        int col = nt * 8 + 2 * tg;
        *(uint32_t*)&ob0[col] = pack_h2(o[nt][0] * inv0, o[nt][1] * inv0);
        *(uint32_t*)&ob1[col] = pack_h2(o[nt][2] * inv1, o[nt][3] * inv1);
    }
}

// ---------------------------------------------------------------------------
extern "C" void kernel_launch(void* const* d_in, const int* in_sizes, int n_in,
                              void* d_out, int out_size)
{
    const float* x  = (const float*)d_in[0];
    const float* Wq = (const float*)d_in[1];
    const float* Wk = (const float*)d_in[2];
    const float* Wv = (const float*)d_in[3];
    const float* Wp = (const float*)d_in[4];
    const float* bp = (const float*)d_in[5];
    float* out = (float*)d_out;

    (void)in_sizes; (void)n_in; (void)out_size;

    __half *d_xh, *d_wqh, *d_wkh, *d_wvh, *d_wph;
    cudaGetSymbolAddress((void**)&d_xh,  g_xh);
    cudaGetSymbolAddress((void**)&d_wqh, g_wqh);
    cudaGetSymbolAddress((void**)&d_wkh, g_wkh);
    cudaGetSymbolAddress((void**)&d_wvh, g_wvh);
    cudaGetSymbolAddress((void**)&d_wph, g_wph);

    // 0) fp32 -> fp16 conversion pre-pass
    cvt_kernel<<<1024, 256>>>((const float4*)x,  (uint2*)d_xh,  MM * CC / 4);
    cvt_kernel<<<256,  256>>>((const float4*)Wq, (uint2*)d_wqh, HH * CC * DD / 4);
    cvt_kernel<<<256,  256>>>((const float4*)Wk, (uint2*)d_wkh, HH * CC * DD / 4);
    cvt_kernel<<<256,  256>>>((const float4*)Wv, (uint2*)d_wvh, HH * CC * DD / 4);
    cvt_kernel<<<256,  256>>>((const float4*)Wp, (uint2*)d_wph, CC * CC / 4);

    // 1) fused QKV projections (fp16 MMA, cp.async): N=3072, M=4096
    gemm_tc<1><<<dim3(24, 32), 128>>>(nullptr, nullptr);

    // 2) causal flash attention (fp16 MMA, cp.async double-buffered K/V)
    attn_tc<<<dim3(32, 32), 128>>>();

    // 3) output projection + bias: N=1024
    gemm_tc<0><<<dim3(8, 32), 128>>>(bp, out);
}

// round 10
// speedup vs baseline: 11.3432x; 1.2770x over previous
#include <cuda_runtime.h>
#include <cuda_fp16.h>
#include <cstdint>

// Problem constants
#define BB 2
#define TT 2048
#define CC 1024
#define HH 16
#define DD 64
#define MM (BB*TT)

// Scratch (static __device__ — no runtime allocation). fp16 everywhere.
__device__ __half g_xh[MM*CC];
__device__ __half g_wqh[HH*CC*DD];
__device__ __half g_wkh[HH*CC*DD];
__device__ __half g_wvh[HH*CC*DD];
__device__ __half g_wph[CC*CC];
__device__ __half g_q[BB*HH*TT*DD];     // [B,H,T,D]
__device__ __half g_k[BB*HH*TT*DD];
__device__ __half g_v[BB*HH*TT*DD];
__device__ __half g_att[BB*TT*CC];      // [B,T,C]

// ---------------------------------------------------------------------------
// helpers
// ---------------------------------------------------------------------------
__device__ __forceinline__ void mma_f16(float* d, const uint32_t* a, const uint32_t* b) {
    asm volatile(
        "mma.sync.aligned.m16n8k16.row.col.f32.f16.f16.f32 "
        "{%0,%1,%2,%3}, {%4,%5,%6,%7}, {%8,%9}, {%0,%1,%2,%3};"
        : "+f"(d[0]), "+f"(d[1]), "+f"(d[2]), "+f"(d[3])
        : "r"(a[0]), "r"(a[1]), "r"(a[2]), "r"(a[3]),
          "r"(b[0]), "r"(b[1]));
}
__device__ __forceinline__ void ldm_x4(uint32_t* r, uint32_t addr) {
    asm volatile(
        "ldmatrix.sync.aligned.m8n8.x4.shared.b16 {%0,%1,%2,%3}, [%4];"
        : "=r"(r[0]), "=r"(r[1]), "=r"(r[2]), "=r"(r[3]) : "r"(addr));
}
__device__ __forceinline__ void ldm_x4_t(uint32_t* r, uint32_t addr) {
    asm volatile(
        "ldmatrix.sync.aligned.m8n8.x4.trans.shared.b16 {%0,%1,%2,%3}, [%4];"
        : "=r"(r[0]), "=r"(r[1]), "=r"(r[2]), "=r"(r[3]) : "r"(addr));
}
__device__ __forceinline__ uint32_t pack_h2(float a, float b) {
    __half2 h = __floats2half2_rn(a, b);
    return *(uint32_t*)&h;
}
__device__ __forceinline__ void cp16(uint32_t dst, const void* src) {
    asm volatile("cp.async.cg.shared.global [%0], [%1], 16;" :: "r"(dst), "l"(src));
}
__device__ __forceinline__ void cp_commit() {
    asm volatile("cp.async.commit_group;");
}
template<int N> __device__ __forceinline__ void cp_wait() {
    asm volatile("cp.async.wait_group %0;" :: "n"(N));
}

// ---------------------------------------------------------------------------
// Fused fp32 -> fp16 conversion (one launch for all five tensors)
// ---------------------------------------------------------------------------
__global__ void cvt_all(const float4* __restrict__ x,  const float4* __restrict__ wq,
                        const float4* __restrict__ wk, const float4* __restrict__ wv,
                        const float4* __restrict__ wp)
{
    const int N_X = MM * CC / 4;        // 1048576
    const int N_W = HH * CC * DD / 4;   // 262144
    const int N_P = CC * CC / 4;        // 262144
    const int total = N_X + 3 * N_W + N_P;
    int i = blockIdx.x * blockDim.x + threadIdx.x;
    const int stride = gridDim.x * blockDim.x;
    for (; i < total; i += stride) {
        const float4* src; uint2* dst; int j = i;
        if (j < N_X)              { src = x;  dst = (uint2*)g_xh; }
        else if ((j -= N_X) < N_W){ src = wq; dst = (uint2*)g_wqh; }
        else if ((j -= N_W) < N_W){ src = wk; dst = (uint2*)g_wkh; }
        else if ((j -= N_W) < N_W){ src = wv; dst = (uint2*)g_wvh; }
        else                      { j -= N_W; src = wp; dst = (uint2*)g_wph; }
        float4 v = src[j];
        uint2 r;
        r.x = pack_h2(v.x, v.y);
        r.y = pack_h2(v.z, v.w);
        dst[j] = r;
    }
}

// ---------------------------------------------------------------------------
// GEMM (fp16 MMA, 3-stage cp.async, BK=16, ONE barrier per iteration).
// BM=128, BN=128. 128 threads = 4 warps; warp tile 64(m) x 64(n).
// SA_H=24: 48B rows, 16B-aligned, ldmatrix row banks 12r mod 32 distinct.
// ---------------------------------------------------------------------------
#define SA_H 24
#define SB_H 136
#define NSTG 3

template<int IS_QKV>
__global__ __launch_bounds__(128, 2) void gemm_tc(
    const float* __restrict__ bp,
    float* __restrict__ out)
{
    __shared__ __half As[NSTG][128 * SA_H];   // 3 x 6.0 KB
    __shared__ __half Bs[NSTG][16 * SB_H];    // 3 x 4.25 KB  (31.5 KB total)

    const int tid  = threadIdx.x;
    const int lane = tid & 31;
    const int warp = tid >> 5;
    const int wm = warp & 1;
    const int wn = warp >> 1;
    const int g  = lane >> 2;
    const int tg = lane & 3;

    const int m0 = blockIdx.y * 128;
    const int n0 = blockIdx.x * 128;

    const __half* A = IS_QKV ? g_xh : g_att;
    const __half* W;
    int h0 = 0, sel = 0;
    if (IS_QKV) {
        sel = n0 >> 10;
        h0  = (n0 & 1023) >> 6;
        W   = (sel == 0 ? g_wqh : (sel == 1 ? g_wkh : g_wvh));
    } else {
        W = g_wph;
    }

    // cp.async mapping: A 128x16 halves (256 chunks), B 16x128 (256 chunks)
    const int a_r  = tid >> 1;              // 0..63 (+64)
    const int a_c8 = (tid & 1) * 8;
    const int b_r  = tid >> 4;              // 0..7 (+8)
    const int b_c8 = (tid & 15) * 8;

    const int lrow  = (lane & 7) + ((lane >> 3) & 1) * 8;
    const int lcol8 = ((lane >> 4) & 1) * 8;
    const uint32_t a_base = (uint32_t)__cvta_generic_to_shared(&As[0][0]);
    const uint32_t b_base = (uint32_t)__cvta_generic_to_shared(&Bs[0][0]);
    const uint32_t ABUF = 128 * SA_H * 2;
    const uint32_t BBUF = 16 * SB_H * 2;

    auto load_stage = [&](int k0, int st) {
        #pragma unroll
        for (int p = 0; p < 2; p++) {
            int r = a_r + p * 64;
            cp16(a_base + st * ABUF + (r * SA_H + a_c8) * 2,
                 &A[(m0 + r) * CC + k0 + a_c8]);
        }
        #pragma unroll
        for (int p = 0; p < 2; p++) {
            int r = b_r + p * 8;
            const __half* src;
            if (IS_QKV) {
                int h = h0 + (b_c8 >> 6);
                int d = b_c8 & 63;
                src = &W[(h * CC + (k0 + r)) * DD + d];
            } else {
                src = &W[(k0 + r) * CC + n0 + b_c8];
            }
            cp16(b_base + st * BBUF + (r * SB_H + b_c8) * 2, src);
        }
    };

    float acc[4][8][4] = {};

    // prologue: 2 real groups
    load_stage(0, 0);  cp_commit();
    load_stage(16, 1); cp_commit();

    const int NIT = CC / 16;   // 64
    for (int it = 0; it < NIT; it++) {
        cp_wait<1>();          // stage it's group retired
        __syncthreads();       // all warps done with stage (it-1)'s reads

        if (it + 2 < NIT) load_stage((it + 2) * 16, (it + 2) % NSTG);
        cp_commit();           // empty group on tail keeps wait invariant

        const int st = it % NSTG;
        uint32_t af[4][4];
        #pragma unroll
        for (int mt = 0; mt < 4; mt++) {
            int row = wm * 64 + mt * 16 + lrow;
            ldm_x4(af[mt], a_base + st * ABUF + (row * SA_H + lcol8) * 2);
        }
        uint32_t bf[4][4];
        #pragma unroll
        for (int np = 0; np < 4; np++) {
            int col = wn * 64 + np * 16 + lcol8;
            ldm_x4_t(bf[np], b_base + st * BBUF + (lrow * SB_H + col) * 2);
        }
        #pragma unroll
        for (int nt = 0; nt < 8; nt++) {
            const uint32_t* bb = &bf[nt >> 1][(nt & 1) * 2];
            #pragma unroll
            for (int mt = 0; mt < 4; mt++)
                mma_f16(acc[mt][nt], af[mt], bb);
        }
    }

    // ---- epilogue ----
    #pragma unroll
    for (int mt = 0; mt < 4; mt++) {
        int mm = m0 + wm * 64 + mt * 16 + g;
        if (IS_QKV) {
            __half* outBuf = (sel == 0 ? g_q : (sel == 1 ? g_k : g_v));
            int b = mm >> 11;
            int t = mm & 2047;
            int h = h0 + wn;
            #pragma unroll
            for (int nt = 0; nt < 8; nt++) {
                int d = nt * 8 + 2 * tg;
                *(uint32_t*)&outBuf[((b * HH + h) * TT + t) * DD + d] =
                    pack_h2(acc[mt][nt][0], acc[mt][nt][1]);
                *(uint32_t*)&outBuf[((b * HH + h) * TT + t + 8) * DD + d] =
                    pack_h2(acc[mt][nt][2], acc[mt][nt][3]);
            }
        } else {
            #pragma unroll
            for (int nt = 0; nt < 8; nt++) {
                int col = n0 + wn * 64 + nt * 8 + 2 * tg;
                float b0 = bp[col], b1 = bp[col + 1];
                *(float2*)&out[mm * CC + col] =
                    make_float2(acc[mt][nt][0] + b0, acc[mt][nt][1] + b1);
                *(float2*)&out[(mm + 8) * CC + col] =
                    make_float2(acc[mt][nt][2] + b0, acc[mt][nt][3] + b1);
            }
        }
    }
}

// ---------------------------------------------------------------------------
// Flash attention (causal), fp16 MMA, 3-stage swizzled KV pipeline,
// ONE barrier per key tile. 64x64-half tiles, 128B rows, SW128 XOR swizzle.
// Softmax in exp2 domain (log2(e)/8 folded into Q scale).
// ---------------------------------------------------------------------------
#define KVSTG 3

__device__ __forceinline__ uint32_t swz(int row, int chunk) {
    // byte offset of 16B chunk within a 64x64-half tile (128B rows)
    return (uint32_t)(row * 128 + ((chunk ^ (row & 7)) << 4));
}

__global__ __launch_bounds__(128, 3) void attn_tc()
{
    __shared__ __half Ks[KVSTG][64 * 64];   // 3 x 8 KB
    __shared__ __half Vs[KVSTG][64 * 64];   // 3 x 8 KB  (48 KB total)

    const int tid  = threadIdx.x;
    const int lane = tid & 31;
    const int warp = tid >> 5;
    const int g  = lane >> 2;
    const int tg = lane & 3;

    const int qt  = blockIdx.x;
    const int bh  = blockIdx.y;
    const int qt0 = qt * 64;

    const uint32_t ks_base = (uint32_t)__cvta_generic_to_shared(&Ks[0][0]);
    const uint32_t vs_base = (uint32_t)__cvta_generic_to_shared(&Vs[0][0]);
    const uint32_t KBUF = 64 * 64 * 2;      // 8192
    const int lrowA  = (lane & 7) + ((lane >> 3) & 1) * 8;
    const int lcol8A = ((lane >> 4) & 1) * 8;
    const int lrowK  = (lane & 7) + ((lane >> 4) & 1) * 8;
    const int lcol8K = ((lane >> 3) & 1) * 8;

    // cp.async mapping: 64 rows x 8 chunks; 4 passes of 128
    const int t_r = tid >> 3;               // 0..15 (+16 per pass)
    const int t_c = tid & 7;                // chunk 0..7

    auto load_kv = [&](int jt, int st) {
        const __half* kb = &g_k[(bh * TT + jt * 64) * DD];
        const __half* vb = &g_v[(bh * TT + jt * 64) * DD];
        #pragma unroll
        for (int p = 0; p < 4; p++) {
            int r = t_r + p * 16;
            cp16(ks_base + st * KBUF + swz(r, t_c), &kb[r * DD + t_c * 8]);
            cp16(vs_base + st * KBUF + swz(r, t_c), &vb[r * DD + t_c * 8]);
        }
    };

    // --- stage Q (scale = log2(e)/8 folded) into Ks[0], extract A-frags ---
    {
        const __half* qb = &g_q[(bh * TT + qt0) * DD];
        const __half2 sc2 = __floats2half2_rn(0.18033688f, 0.18033688f);
        #pragma unroll
        for (int p = 0; p < 4; p++) {
            int idx = tid + p * 128;
            int r = idx >> 3, c = idx & 7;
            uint4 v = *(const uint4*)&qb[r * DD + c * 8];
            __half2* hp = (__half2*)&v;
            #pragma unroll
            for (int i = 0; i < 4; i++) hp[i] = __hmul2(hp[i], sc2);
            *(uint4*)((char*)&Ks[0][0] + swz(r, c)) = v;
        }
    }
    __syncthreads();
    uint32_t qa[4][4];
    #pragma unroll
    for (int kc = 0; kc < 4; kc++) {
        int row = warp * 16 + lrowA;
        int ch  = 2 * kc + (lcol8A >> 3);
        ldm_x4(qa[kc], ks_base + swz(row, ch));
    }
    __syncthreads();            // Q reads done before Ks[0] reused for K

    // prologue: 2 real groups (guard jt=1 for qt=0)
    load_kv(0, 0); cp_commit();
    if (qt >= 1) load_kv(1, 1);
    cp_commit();

    float o[8][4] = {};
    float m0v = -1e30f, m1v = -1e30f, l0 = 0.f, l1 = 0.f;
    const int i0 = qt0 + warp * 16 + g;
    const int i1 = i0 + 8;

    for (int jt = 0; jt <= qt; jt++) {
        cp_wait<1>();
        __syncthreads();

        if (jt + 2 <= qt) load_kv(jt + 2, (jt + 2) % KVSTG);
        cp_commit();

        const int st = jt % KVSTG;
        const uint32_t kst = ks_base + st * KBUF;
        const uint32_t vst = vs_base + st * KBUF;

        // --- S = Q K^T (log2 domain) ---
        float s[8][4] = {};
        #pragma unroll
        for (int kc = 0; kc < 4; kc++) {
            uint32_t kf[4][4];
            #pragma unroll
            for (int np = 0; np < 4; np++) {
                int key = np * 16 + lrowK;
                int ch  = 2 * kc + (lcol8K >> 3);
                ldm_x4(kf[np], kst + swz(key, ch));
            }
            #pragma unroll
            for (int nt = 0; nt < 8; nt++)
                mma_f16(s[nt], qa[kc], &kf[nt >> 1][(nt & 1) * 2]);
        }

        if (jt == qt) {
            #pragma unroll
            for (int nt = 0; nt < 8; nt++) {
                int j = qt0 + nt * 8 + 2 * tg;
                if (j     > i0) s[nt][0] = -1e30f;
                if (j + 1 > i0) s[nt][1] = -1e30f;
                if (j     > i1) s[nt][2] = -1e30f;
                if (j + 1 > i1) s[nt][3] = -1e30f;
            }
        }

        // --- online softmax (exp2 domain) ---
        float rmax0 = -1e30f, rmax1 = -1e30f;
        #pragma unroll
        for (int nt = 0; nt < 8; nt++) {
            rmax0 = fmaxf(rmax0, fmaxf(s[nt][0], s[nt][1]));
            rmax1 = fmaxf(rmax1, fmaxf(s[nt][2], s[nt][3]));
        }
        rmax0 = fmaxf(rmax0, __shfl_xor_sync(0xffffffffu, rmax0, 1));
        rmax0 = fmaxf(rmax0, __shfl_xor_sync(0xffffffffu, rmax0, 2));
        rmax1 = fmaxf(rmax1, __shfl_xor_sync(0xffffffffu, rmax1, 1));
        rmax1 = fmaxf(rmax1, __shfl_xor_sync(0xffffffffu, rmax1, 2));

        float mn0 = fmaxf(m0v, rmax0);
        float mn1 = fmaxf(m1v, rmax1);
        float al0 = exp2f(m0v - mn0);
        float al1 = exp2f(m1v - mn1);

        float ls0 = 0.f, ls1 = 0.f;
        #pragma unroll
        for (int nt = 0; nt < 8; nt++) {
            s[nt][0] = exp2f(s[nt][0] - mn0);
            s[nt][1] = exp2f(s[nt][1] - mn0);
            s[nt][2] = exp2f(s[nt][2] - mn1);
            s[nt][3] = exp2f(s[nt][3] - mn1);
            ls0 += s[nt][0] + s[nt][1];
            ls1 += s[nt][2] + s[nt][3];
        }
        ls0 += __shfl_xor_sync(0xffffffffu, ls0, 1);
        ls0 += __shfl_xor_sync(0xffffffffu, ls0, 2);
        ls1 += __shfl_xor_sync(0xffffffffu, ls1, 1);
        ls1 += __shfl_xor_sync(0xffffffffu, ls1, 2);

        l0 = l0 * al0 + ls0;  m0v = mn0;
        l1 = l1 * al1 + ls1;  m1v = mn1;

        #pragma unroll
        for (int nt = 0; nt < 8; nt++) {
            o[nt][0] *= al0; o[nt][1] *= al0;
            o[nt][2] *= al1; o[nt][3] *= al1;
        }

        // --- O += P V (direct pack of S into A-frags) ---
        #pragma unroll
        for (int kc = 0; kc < 4; kc++) {
            uint32_t pa[4];
            pa[0] = pack_h2(s[2*kc  ][0], s[2*kc  ][1]);
            pa[1] = pack_h2(s[2*kc  ][2], s[2*kc  ][3]);
            pa[2] = pack_h2(s[2*kc+1][0], s[2*kc+1][1]);
            pa[3] = pack_h2(s[2*kc+1][2], s[2*kc+1][3]);
            uint32_t vf[4][4];
            #pragma unroll
            for (int np = 0; np < 4; np++) {
                int key = kc * 16 + lrowA;
                int ch  = 2 * np + (lcol8A >> 3);
                ldm_x4_t(vf[np], vst + swz(key, ch));
            }
            #pragma unroll
            for (int nt = 0; nt < 8; nt++)
                mma_f16(o[nt], pa, &vf[nt >> 1][(nt & 1) * 2]);
        }
    }

    // --- normalize + store to g_att ---
    const float inv0 = 1.f / l0;
    const float inv1 = 1.f / l1;
    const int b = bh >> 4;
    const int h = bh & 15;
    const int r0 = qt0 + warp * 16 + g;
    __half* ob0 = &g_att[(b * TT + r0) * CC + h * DD];
    __half* ob1 = &g_att[(b * TT + r0 + 8) * CC + h * DD];
    #pragma unroll
    for (int nt = 0; nt < 8; nt++) {
        int col = nt * 8 + 2 * tg;
        *(uint32_t*)&ob0[col] = pack_h2(o[nt][0] * inv0, o[nt][1] * inv0);
        *(uint32_t*)&ob1[col] = pack_h2(o[nt][2] * inv1, o[nt][3] * inv1);
    }
}

// ---------------------------------------------------------------------------
extern "C" void kernel_launch(void* const* d_in, const int* in_sizes, int n_in,
                              void* d_out, int out_size)
{
    const float* x  = (const float*)d_in[0];
    const float* Wq = (const float*)d_in[1];
    const float* Wk = (const float*)d_in[2];
    const float* Wv = (const float*)d_in[3];
    const float* Wp = (const float*)d_in[4];
    const float* bp = (const float*)d_in[5];
    float* out = (float*)d_out;

    (void)in_sizes; (void)n_in; (void)out_size;

    // 0) one fused fp32 -> fp16 conversion pass
    cvt_all<<<2048, 256>>>((const float4*)x,  (const float4*)Wq,
                           (const float4*)Wk, (const float4*)Wv,
                           (const float4*)Wp);

    // 1) fused QKV projections (fp16 MMA, 3-stage): N=3072, M=4096
    gemm_tc<1><<<dim3(24, 32), 128>>>(nullptr, nullptr);

    // 2) causal flash attention (fp16 MMA, 3-stage swizzled KV)
    attn_tc<<<dim3(32, 32), 128>>>();

    // 3) output projection + bias (fp16 MMA, 3-stage): N=1024
    gemm_tc<0><<<dim3(8, 32), 128>>>(bp, out);
}